// round 1
// baseline (speedup 1.0000x reference)
#include <cuda_runtime.h>
#include <cuda_bf16.h>

#define Bb   2
#define Cc   64
#define Nn   2304
#define Hh   4
#define Dh   16
#define BH   (Bb*Hh)
#define MLP  256
#define NTILE 18            // Nn / 128

// ---------------- scratch (device globals; no allocation) ----------------
__device__ float g_xt [Bb*Nn*Cc];      // x transposed (b, n, c)
__device__ float g_y1 [BH*Nn*Dh];
__device__ float g_y2 [BH*Nn*Dh];
__device__ float g_x1 [BH*Nn*Dh];
__device__ float g_x2 [BH*Nn*Dh];
__device__ float g_secp[BH*NTILE*256]; // channel-attn partial sums
__device__ float g_secm[BH*256];       // softmaxed 16x16 channel maps
__device__ float g_out[Bb*Nn*Cc];      // out1*out2 in (b, n, inner)

// ---------------- K1: transpose + LayerNorm + 4 projections ----------------
__global__ __launch_bounds__(64) void k_ln_proj(
    const float* __restrict__ x, const float* __restrict__ y,
    const float* __restrict__ g, const float* __restrict__ be,
    const float* __restrict__ wsa1, const float* __restrict__ wsa2,
    const float* __restrict__ wse1, const float* __restrict__ wse2)
{
    const int t = threadIdx.x;
    const int row0 = blockIdx.x * 4;
    __shared__ float sxn[4][64], syn[4][64];
    __shared__ float sred[2][16];

    float xv[4], yv[4];
#pragma unroll
    for (int r = 0; r < 4; r++) {
        int row = row0 + r;
        int b = row / Nn, nidx = row - b * Nn;
        xv[r] = x[((size_t)b*Cc + t)*Nn + nidx];
        yv[r] = y[((size_t)b*Cc + t)*Nn + nidx];
        g_xt[(size_t)row*Cc + t] = xv[r];
    }
    const int wid = t >> 5, lane = t & 31;
#pragma unroll
    for (int r = 0; r < 4; r++) {
        float a = xv[r], a2 = a*a, bb = yv[r], b2v = bb*bb;
#pragma unroll
        for (int o = 16; o > 0; o >>= 1) {
            a   += __shfl_xor_sync(0xffffffffu, a,   o);
            a2  += __shfl_xor_sync(0xffffffffu, a2,  o);
            bb  += __shfl_xor_sync(0xffffffffu, bb,  o);
            b2v += __shfl_xor_sync(0xffffffffu, b2v, o);
        }
        if (lane == 0) {
            sred[wid][r*4+0] = a;  sred[wid][r*4+1] = a2;
            sred[wid][r*4+2] = bb; sred[wid][r*4+3] = b2v;
        }
    }
    __syncthreads();
    const float gt = g[t], bet = be[t];
#pragma unroll
    for (int r = 0; r < 4; r++) {
        float sx  = sred[0][r*4+0] + sred[1][r*4+0];
        float sx2 = sred[0][r*4+1] + sred[1][r*4+1];
        float sy  = sred[0][r*4+2] + sred[1][r*4+2];
        float sy2 = sred[0][r*4+3] + sred[1][r*4+3];
        float mx = sx*(1.f/64.f), vx = sx2*(1.f/64.f) - mx*mx;
        float my = sy*(1.f/64.f), vy = sy2*(1.f/64.f) - my*my;
        float rx = rsqrtf(vx + 1e-5f), ry = rsqrtf(vy + 1e-5f);
        sxn[r][t] = (xv[r]-mx)*rx*gt + bet;
        syn[r][t] = (yv[r]-my)*ry*gt + bet;
    }
    __syncthreads();

    float a1[4] = {0,0,0,0}, a2a[4] = {0,0,0,0}, a3[4] = {0,0,0,0}, a4[4] = {0,0,0,0};
#pragma unroll 4
    for (int c = 0; c < 64; c++) {
        float w1v = wsa1[c*64+t], w2v = wsa2[c*64+t];
        float w3v = wse1[c*64+t], w4v = wse2[c*64+t];
#pragma unroll
        for (int r = 0; r < 4; r++) {
            float yc = syn[r][c], xc = sxn[r][c];
            a1[r]  = fmaf(yc, w1v, a1[r]);
            a2a[r] = fmaf(yc, w2v, a2a[r]);
            a3[r]  = fmaf(xc, w3v, a3[r]);
            a4[r]  = fmaf(xc, w4v, a4[r]);
        }
    }
    const int h = t >> 4, d = t & 15;
#pragma unroll
    for (int r = 0; r < 4; r++) {
        int row = row0 + r;
        int b = row / Nn, nidx = row - b * Nn;
        size_t o = ((size_t)(b*Hh + h)*Nn + nidx)*Dh + d;
        g_y1[o] = a1[r]; g_y2[o] = a2a[r];
        g_x1[o] = a3[r]; g_x2[o] = a4[r];
    }
}

// ---------------- K2a: channel-attn logits, partial over n-tiles ----------------
__global__ __launch_bounds__(256) void k_secm_part()
{
    const int bh = blockIdx.y, nb = blockIdx.x;
    const int t = threadIdx.x, i = t >> 4, j = t & 15;
    const float* __restrict__ x1 = g_x1 + (size_t)bh*Nn*Dh;
    const float* __restrict__ x2 = g_x2 + (size_t)bh*Nn*Dh;
    const int n0 = nb * 128;
    float s = 0.f;
#pragma unroll 4
    for (int n = n0; n < n0 + 128; n++)
        s = fmaf(x1[n*16 + i], x2[n*16 + j], s);
    g_secp[((size_t)bh*NTILE + nb)*256 + t] = s;
}

// ---------------- K2b: reduce partials + softmax (16x16 per bh) ----------------
__global__ __launch_bounds__(256) void k_secm_soft()
{
    const int bh = blockIdx.x;
    const int t = threadIdx.x, i = t >> 4;
    float s = 0.f;
#pragma unroll
    for (int k = 0; k < NTILE; k++)
        s += g_secp[((size_t)bh*NTILE + k)*256 + t];
    s *= (0.25f / 144.0f);
    __shared__ float sm[16][16], se[16][16];
    sm[i][t & 15] = s;
    __syncthreads();
    float rmax = -1e30f;
#pragma unroll
    for (int k = 0; k < 16; k++) rmax = fmaxf(rmax, sm[i][k]);
    float e = __expf(s - rmax);
    se[i][t & 15] = e;
    __syncthreads();
    float rs = 0.f;
#pragma unroll
    for (int k = 0; k < 16; k++) rs += se[i][k];
    g_secm[bh*256 + t] = e / rs;
}

// ---------------- K3: flash spatial attention + out2 fuse + combine ----------------
__global__ __launch_bounds__(256) void k_flash()
{
    const int bh = blockIdx.y, qt = blockIdx.x;
    const int t = threadIdx.x, lane = t & 127, half = t >> 7;

    __shared__ float4 sk[2][128][4];
    __shared__ float4 sv[2][128][4];
    __shared__ float  ssec[16][16];
    __shared__ float  red[128][17];

    ssec[t >> 4 & 15][t & 15] = g_secm[bh*256 + (t & 255)];

    const float* __restrict__ Qb = g_y1 + (size_t)bh*Nn*Dh;
    const float* __restrict__ Kb = g_y2 + (size_t)bh*Nn*Dh;
    const float* __restrict__ Vb = g_x1 + (size_t)bh*Nn*Dh;

    const int q = qt*128 + lane;
    const float4* qp = (const float4*)(Qb + (size_t)q*16);
    float4 q0 = qp[0], q1 = qp[1], q2 = qp[2], q3 = qp[3];

    float aa[16];
#pragma unroll
    for (int k = 0; k < 16; k++) aa[k] = 0.f;
    float l = 0.f;

    const int kb0 = half * (Nn/2);
    for (int tile = 0; tile < 9; tile++) {
        const int kb = kb0 + tile*128;
        const float4* gk = (const float4*)(Kb + (size_t)kb*16);
        const float4* gv = (const float4*)(Vb + (size_t)kb*16);
        float4* skl = (float4*)sk[half];
        float4* svl = (float4*)sv[half];
#pragma unroll
        for (int s2 = 0; s2 < 4; s2++) {
            skl[lane + s2*128] = gk[lane + s2*128];
            svl[lane + s2*128] = gv[lane + s2*128];
        }
        __syncthreads();
#pragma unroll 4
        for (int j = 0; j < 128; j++) {
            float4 k0 = sk[half][j][0], k1 = sk[half][j][1];
            float4 k2 = sk[half][j][2], k3 = sk[half][j][3];
            float d0 = fmaf(q0.w,k0.w, fmaf(q0.z,k0.z, fmaf(q0.y,k0.y, q0.x*k0.x)));
            float d1 = fmaf(q1.w,k1.w, fmaf(q1.z,k1.z, fmaf(q1.y,k1.y, q1.x*k1.x)));
            float d2 = fmaf(q2.w,k2.w, fmaf(q2.z,k2.z, fmaf(q2.y,k2.y, q2.x*k2.x)));
            float d3 = fmaf(q3.w,k3.w, fmaf(q3.z,k3.z, fmaf(q3.y,k3.y, q3.x*k3.x)));
            // logits are small by construction -> max-free softmax is safe in fp32
            float p = __expf(((d0+d1)+(d2+d3)) * 0.25f);
            l += p;
            float4 v0 = sv[half][j][0], v1 = sv[half][j][1];
            float4 v2 = sv[half][j][2], v3 = sv[half][j][3];
            aa[0]  = fmaf(p, v0.x, aa[0]);  aa[1]  = fmaf(p, v0.y, aa[1]);
            aa[2]  = fmaf(p, v0.z, aa[2]);  aa[3]  = fmaf(p, v0.w, aa[3]);
            aa[4]  = fmaf(p, v1.x, aa[4]);  aa[5]  = fmaf(p, v1.y, aa[5]);
            aa[6]  = fmaf(p, v1.z, aa[6]);  aa[7]  = fmaf(p, v1.w, aa[7]);
            aa[8]  = fmaf(p, v2.x, aa[8]);  aa[9]  = fmaf(p, v2.y, aa[9]);
            aa[10] = fmaf(p, v2.z, aa[10]); aa[11] = fmaf(p, v2.w, aa[11]);
            aa[12] = fmaf(p, v3.x, aa[12]); aa[13] = fmaf(p, v3.y, aa[13]);
            aa[14] = fmaf(p, v3.z, aa[14]); aa[15] = fmaf(p, v3.w, aa[15]);
        }
        __syncthreads();
    }

    if (half == 1) {
        float* rp = red[lane];
#pragma unroll
        for (int k = 0; k < 16; k++) rp[k] = aa[k];
        rp[16] = l;
    }
    __syncthreads();
    if (half == 0) {
        const float* rp = red[lane];
#pragma unroll
        for (int k = 0; k < 16; k++) aa[k] += rp[k];
        l += rp[16];
        float inv = 1.0f / l;

        float qa[16] = { q0.x,q0.y,q0.z,q0.w, q1.x,q1.y,q1.z,q1.w,
                         q2.x,q2.y,q2.z,q2.w, q3.x,q3.y,q3.z,q3.w };
        float o2[16];
#pragma unroll
        for (int jj = 0; jj < 16; jj++) {
            float acc = 0.f;
#pragma unroll
            for (int ii = 0; ii < 16; ii++)
                acc = fmaf(qa[ii], ssec[ii][jj], acc);
            o2[jj] = acc;
        }
        const int b = bh >> 2, h = bh & 3;
        float* op = g_out + ((size_t)(b*Nn + q))*64 + h*16;
#pragma unroll
        for (int k = 0; k < 16; k++)
            op[k] = aa[k] * inv * o2[k];
    }
}

// ---------------- K4: out-proj + residual + LN2 + MLP + residual + transpose ----------------
__device__ __forceinline__ float leaky(float h) { return h > 0.f ? h : 0.01f * h; }

__global__ __launch_bounds__(64) void k_tail(
    const float* __restrict__ wout, const float* __restrict__ bout,
    const float* __restrict__ g2,   const float* __restrict__ be2,
    const float* __restrict__ w1,   const float* __restrict__ b1,
    const float* __restrict__ w2,   const float* __restrict__ b2,
    float* __restrict__ out)
{
    const int t = threadIdx.x;
    const int row0 = blockIdx.x * 4;
    __shared__ float so[4][64];
    __shared__ float sn[4][64];
    __shared__ float sh[4][256];
    __shared__ float sred[2][8];

#pragma unroll
    for (int r = 0; r < 4; r++) so[r][t] = g_out[(size_t)(row0+r)*64 + t];
    __syncthreads();

    float accP[4] = {0,0,0,0};
#pragma unroll 4
    for (int c = 0; c < 64; c++) {
        float w = wout[c*64 + t];
#pragma unroll
        for (int r = 0; r < 4; r++) accP[r] = fmaf(so[r][c], w, accP[r]);
    }
    const float bo = bout[t];
    float x2v[4];
#pragma unroll
    for (int r = 0; r < 4; r++)
        x2v[r] = g_xt[(size_t)(row0+r)*64 + t] + accP[r] + bo;

    const int wid = t >> 5, lane = t & 31;
#pragma unroll
    for (int r = 0; r < 4; r++) {
        float a = x2v[r], a2 = a*a;
#pragma unroll
        for (int o = 16; o > 0; o >>= 1) {
            a  += __shfl_xor_sync(0xffffffffu, a,  o);
            a2 += __shfl_xor_sync(0xffffffffu, a2, o);
        }
        if (lane == 0) { sred[wid][r*2] = a; sred[wid][r*2+1] = a2; }
    }
    __syncthreads();
    const float g2t = g2[t], be2t = be2[t];
#pragma unroll
    for (int r = 0; r < 4; r++) {
        float sxx = sred[0][r*2] + sred[1][r*2];
        float sq  = sred[0][r*2+1] + sred[1][r*2+1];
        float m = sxx*(1.f/64.f), v = sq*(1.f/64.f) - m*m;
        sn[r][t] = (x2v[r]-m)*rsqrtf(v + 1e-5f)*g2t + be2t;
    }
    __syncthreads();

    float h0[4], h1[4], h2[4], h3[4];
    const float bb0 = b1[t], bb1 = b1[t+64], bb2 = b1[t+128], bb3 = b1[t+192];
#pragma unroll
    for (int r = 0; r < 4; r++) { h0[r]=bb0; h1[r]=bb1; h2[r]=bb2; h3[r]=bb3; }
#pragma unroll 2
    for (int c = 0; c < 64; c++) {
        float w0 = w1[c*256 + t], w1v = w1[c*256 + t + 64];
        float w2v = w1[c*256 + t + 128], w3v = w1[c*256 + t + 192];
#pragma unroll
        for (int r = 0; r < 4; r++) {
            float xn = sn[r][c];
            h0[r] = fmaf(xn, w0,  h0[r]);
            h1[r] = fmaf(xn, w1v, h1[r]);
            h2[r] = fmaf(xn, w2v, h2[r]);
            h3[r] = fmaf(xn, w3v, h3[r]);
        }
    }
#pragma unroll
    for (int r = 0; r < 4; r++) {
        sh[r][t]       = leaky(h0[r]);
        sh[r][t + 64]  = leaky(h1[r]);
        sh[r][t + 128] = leaky(h2[r]);
        sh[r][t + 192] = leaky(h3[r]);
    }
    __syncthreads();

    float f[4] = {0,0,0,0};
#pragma unroll 2
    for (int j = 0; j < 256; j++) {
        float w = w2[j*64 + t];
#pragma unroll
        for (int r = 0; r < 4; r++) f[r] = fmaf(sh[r][j], w, f[r]);
    }
    const float b2t = b2[t];
#pragma unroll
    for (int r = 0; r < 4; r++) {
        int row = row0 + r;
        int b = row / Nn, nidx = row - b * Nn;
        out[((size_t)b*Cc + t)*Nn + nidx] = x2v[r] + f[r] + b2t;
    }
}

// ---------------- launch ----------------
extern "C" void kernel_launch(void* const* d_in, const int* in_sizes, int n_in,
                              void* d_out, int out_size)
{
    (void)in_sizes; (void)n_in; (void)out_size;
    const float* x    = (const float*)d_in[0];
    const float* y    = (const float*)d_in[1];
    const float* ln1g = (const float*)d_in[2];
    const float* ln1b = (const float*)d_in[3];
    const float* wsa1 = (const float*)d_in[4];
    const float* wsa2 = (const float*)d_in[5];
    const float* wse1 = (const float*)d_in[6];
    const float* wse2 = (const float*)d_in[7];
    const float* wout = (const float*)d_in[8];
    const float* bout = (const float*)d_in[9];
    const float* ln2g = (const float*)d_in[10];
    const float* ln2b = (const float*)d_in[11];
    const float* w1   = (const float*)d_in[12];
    const float* b1   = (const float*)d_in[13];
    const float* w2   = (const float*)d_in[14];
    const float* b2   = (const float*)d_in[15];
    float* out = (float*)d_out;

    k_ln_proj<<<Bb*Nn/4, 64>>>(x, y, ln1g, ln1b, wsa1, wsa2, wse1, wse2);
    dim3 gsec(NTILE, BH);
    k_secm_part<<<gsec, 256>>>();
    k_secm_soft<<<BH, 256>>>();
    dim3 gfl(NTILE, BH);
    k_flash<<<gfl, 256>>>();
    k_tail<<<Bb*Nn/4, 64>>>(wout, bout, ln2g, ln2b, w1, b1, w2, b2, out);
}

// round 2
// speedup vs baseline: 1.0891x; 1.0891x over previous
#include <cuda_runtime.h>
#include <cuda_bf16.h>

#define Bb   2
#define Cc   64
#define Nn   2304
#define Hh   4
#define Dh   16
#define BH   (Bb*Hh)
#define MLP  256
#define NTILE 18            // Nn / 128

typedef unsigned long long u64;

// ---------------- packed f32x2 helpers (sm_103a) ----------------
__device__ __forceinline__ u64 fma2(u64 a, u64 b, u64 c) {
    u64 d; asm("fma.rn.f32x2 %0, %1, %2, %3;" : "=l"(d) : "l"(a), "l"(b), "l"(c)); return d;
}
__device__ __forceinline__ u64 mul2(u64 a, u64 b) {
    u64 d; asm("mul.rn.f32x2 %0, %1, %2;" : "=l"(d) : "l"(a), "l"(b)); return d;
}
__device__ __forceinline__ u64 add2(u64 a, u64 b) {
    u64 d; asm("add.rn.f32x2 %0, %1, %2;" : "=l"(d) : "l"(a), "l"(b)); return d;
}
__device__ __forceinline__ float2 unpk(u64 v) {
    float2 r; asm("mov.b64 {%0,%1}, %2;" : "=f"(r.x), "=f"(r.y) : "l"(v)); return r;
}
__device__ __forceinline__ u64 pk(float lo, float hi) {
    u64 v; asm("mov.b64 %0, {%1,%2};" : "=l"(v) : "f"(lo), "f"(hi)); return v;
}

// ---------------- scratch (device globals; no allocation) ----------------
__device__ float g_xt [Bb*Nn*Cc];      // x transposed (b, n, c)
__device__ float g_y1 [BH*Nn*Dh];
__device__ float g_y2 [BH*Nn*Dh];
__device__ float g_x1 [BH*Nn*Dh];
__device__ float g_x2 [BH*Nn*Dh];
__device__ float g_secp[BH*NTILE*256]; // channel-attn partial sums
__device__ float g_secm[BH*256];       // softmaxed 16x16 channel maps
__device__ float g_out[Bb*Nn*Cc];      // out1*out2 in (b, n, inner)

// ---------------- K1: transpose + LayerNorm + 4 projections ----------------
__global__ __launch_bounds__(64) void k_ln_proj(
    const float* __restrict__ x, const float* __restrict__ y,
    const float* __restrict__ g, const float* __restrict__ be,
    const float* __restrict__ wsa1, const float* __restrict__ wsa2,
    const float* __restrict__ wse1, const float* __restrict__ wse2)
{
    const int t = threadIdx.x;
    const int row0 = blockIdx.x * 4;
    __shared__ float sxn[4][64], syn[4][64];
    __shared__ float sred[2][16];

    float xv[4], yv[4];
#pragma unroll
    for (int r = 0; r < 4; r++) {
        int row = row0 + r;
        int b = row / Nn, nidx = row - b * Nn;
        xv[r] = x[((size_t)b*Cc + t)*Nn + nidx];
        yv[r] = y[((size_t)b*Cc + t)*Nn + nidx];
        g_xt[(size_t)row*Cc + t] = xv[r];
    }
    const int wid = t >> 5, lane = t & 31;
#pragma unroll
    for (int r = 0; r < 4; r++) {
        float a = xv[r], a2 = a*a, bb = yv[r], b2v = bb*bb;
#pragma unroll
        for (int o = 16; o > 0; o >>= 1) {
            a   += __shfl_xor_sync(0xffffffffu, a,   o);
            a2  += __shfl_xor_sync(0xffffffffu, a2,  o);
            bb  += __shfl_xor_sync(0xffffffffu, bb,  o);
            b2v += __shfl_xor_sync(0xffffffffu, b2v, o);
        }
        if (lane == 0) {
            sred[wid][r*4+0] = a;  sred[wid][r*4+1] = a2;
            sred[wid][r*4+2] = bb; sred[wid][r*4+3] = b2v;
        }
    }
    __syncthreads();
    const float gt = g[t], bet = be[t];
#pragma unroll
    for (int r = 0; r < 4; r++) {
        float sx  = sred[0][r*4+0] + sred[1][r*4+0];
        float sx2 = sred[0][r*4+1] + sred[1][r*4+1];
        float sy  = sred[0][r*4+2] + sred[1][r*4+2];
        float sy2 = sred[0][r*4+3] + sred[1][r*4+3];
        float mx = sx*(1.f/64.f), vx = sx2*(1.f/64.f) - mx*mx;
        float my = sy*(1.f/64.f), vy = sy2*(1.f/64.f) - my*my;
        float rx = rsqrtf(vx + 1e-5f), ry = rsqrtf(vy + 1e-5f);
        sxn[r][t] = (xv[r]-mx)*rx*gt + bet;
        syn[r][t] = (yv[r]-my)*ry*gt + bet;
    }
    __syncthreads();

    float a1[4] = {0,0,0,0}, a2a[4] = {0,0,0,0}, a3[4] = {0,0,0,0}, a4[4] = {0,0,0,0};
#pragma unroll 4
    for (int c = 0; c < 64; c++) {
        float w1v = wsa1[c*64+t], w2v = wsa2[c*64+t];
        float w3v = wse1[c*64+t], w4v = wse2[c*64+t];
#pragma unroll
        for (int r = 0; r < 4; r++) {
            float yc = syn[r][c], xc = sxn[r][c];
            a1[r]  = fmaf(yc, w1v, a1[r]);
            a2a[r] = fmaf(yc, w2v, a2a[r]);
            a3[r]  = fmaf(xc, w3v, a3[r]);
            a4[r]  = fmaf(xc, w4v, a4[r]);
        }
    }
    const int h = t >> 4, d = t & 15;
#pragma unroll
    for (int r = 0; r < 4; r++) {
        int row = row0 + r;
        int b = row / Nn, nidx = row - b * Nn;
        size_t o = ((size_t)(b*Hh + h)*Nn + nidx)*Dh + d;
        g_y1[o] = a1[r]; g_y2[o] = a2a[r];
        g_x1[o] = a3[r]; g_x2[o] = a4[r];
    }
}

// ---------------- K2a: channel-attn logits, partial over n-tiles ----------------
__global__ __launch_bounds__(256) void k_secm_part()
{
    const int bh = blockIdx.y, nb = blockIdx.x;
    const int t = threadIdx.x, i = t >> 4, j = t & 15;
    const float* __restrict__ x1 = g_x1 + (size_t)bh*Nn*Dh;
    const float* __restrict__ x2 = g_x2 + (size_t)bh*Nn*Dh;
    const int n0 = nb * 128;
    float s = 0.f;
#pragma unroll 4
    for (int n = n0; n < n0 + 128; n++)
        s = fmaf(x1[n*16 + i], x2[n*16 + j], s);
    g_secp[((size_t)bh*NTILE + nb)*256 + t] = s;
}

// ---------------- K2b: reduce partials + softmax (16x16 per bh) ----------------
__global__ __launch_bounds__(256) void k_secm_soft()
{
    const int bh = blockIdx.x;
    const int t = threadIdx.x, i = t >> 4;
    float s = 0.f;
#pragma unroll
    for (int k = 0; k < NTILE; k++)
        s += g_secp[((size_t)bh*NTILE + k)*256 + t];
    s *= (0.25f / 144.0f);
    __shared__ float sm[16][16], se[16][16];
    sm[i][t & 15] = s;
    __syncthreads();
    float rmax = -1e30f;
#pragma unroll
    for (int k = 0; k < 16; k++) rmax = fmaxf(rmax, sm[i][k]);
    float e = __expf(s - rmax);
    se[i][t & 15] = e;
    __syncthreads();
    float rs = 0.f;
#pragma unroll
    for (int k = 0; k < 16; k++) rs += se[i][k];
    g_secm[bh*256 + t] = e / rs;
}

// ---------------- K3: flash spatial attention (f32x2, 2 queries/thread) ----------------
// 512 threads: oct = t>>6 (8-way key split, 288 keys each), lane = t&63.
// Each thread handles queries q0 = qt*128+lane, q1 = q0+64.
// Dynamic smem: sK[8][32][16] + sV[8][32][16] + red[8*128][17]
#define FL_TPB   512
#define FL_KEYS  288          // keys per oct
#define FL_TK    32           // keys per tile
#define FL_NT    (FL_KEYS/FL_TK)  // 9 tiles
#define FL_SK    (8*FL_TK*16)     // floats
#define FL_SMEM  ((2*FL_SK + 8*128*17) * 4)

__global__ __launch_bounds__(FL_TPB) void k_flash()
{
    extern __shared__ float dsm[];
    float* sK  = dsm;
    float* sV  = dsm + FL_SK;
    float* red = dsm + 2*FL_SK;
    __shared__ float ssec[16][16];

    const int bh = blockIdx.y, qt = blockIdx.x;
    const int t = threadIdx.x;
    const int oct = t >> 6, lane = t & 63;

    if (t < 256) ssec[t >> 4][t & 15] = g_secm[bh*256 + t];

    const float* __restrict__ Qb = g_y1 + (size_t)bh*Nn*Dh;
    const float* __restrict__ Kb = g_y2 + (size_t)bh*Nn*Dh;
    const float* __restrict__ Vb = g_x1 + (size_t)bh*Nn*Dh;

    const int q0 = qt*128 + lane;
    const int q1 = q0 + 64;

    // load packed queries
    u64 qq0[8], qq1[8];
    {
        const ulonglong2* qp = (const ulonglong2*)(Qb + (size_t)q0*16);
        ulonglong2 a = qp[0], b = qp[1], c = qp[2], d = qp[3];
        qq0[0]=a.x; qq0[1]=a.y; qq0[2]=b.x; qq0[3]=b.y;
        qq0[4]=c.x; qq0[5]=c.y; qq0[6]=d.x; qq0[7]=d.y;
        qp = (const ulonglong2*)(Qb + (size_t)q1*16);
        a = qp[0]; b = qp[1]; c = qp[2]; d = qp[3];
        qq1[0]=a.x; qq1[1]=a.y; qq1[2]=b.x; qq1[3]=b.y;
        qq1[4]=c.x; qq1[5]=c.y; qq1[6]=d.x; qq1[7]=d.y;
    }

    u64 ac0[8], ac1[8];
    const u64 ZZ = 0ull;
#pragma unroll
    for (int i = 0; i < 8; i++) { ac0[i] = ZZ; ac1[i] = ZZ; }
    float l0 = 0.f, l1 = 0.f;

    float4* skf = (float4*)(sK + oct*FL_TK*16);
    float4* svf = (float4*)(sV + oct*FL_TK*16);

    for (int tile = 0; tile < FL_NT; tile++) {
        const int kb = oct*FL_KEYS + tile*FL_TK;
        const float4* gk = (const float4*)(Kb + (size_t)kb*16);
        const float4* gv = (const float4*)(Vb + (size_t)kb*16);
#pragma unroll
        for (int s = 0; s < 2; s++) {          // 32 keys * 4 float4 = 128 per oct
            skf[lane + s*64] = gk[lane + s*64];
            svf[lane + s*64] = gv[lane + s*64];
        }
        __syncthreads();

        const float* kb_s = sK + oct*FL_TK*16;
        const float* vb_s = sV + oct*FL_TK*16;
#pragma unroll 2
        for (int j = 0; j < FL_TK; j++) {
            const ulonglong2* kp = (const ulonglong2*)(kb_s + j*16);
            ulonglong2 ka = kp[0], kbb = kp[1], kc = kp[2], kd = kp[3];

            u64 d00 = mul2(qq0[0], ka.x);
            u64 d01 = mul2(qq0[1], ka.y);
            u64 d10 = mul2(qq1[0], ka.x);
            u64 d11 = mul2(qq1[1], ka.y);
            d00 = fma2(qq0[2], kbb.x, d00);  d01 = fma2(qq0[3], kbb.y, d01);
            d10 = fma2(qq1[2], kbb.x, d10);  d11 = fma2(qq1[3], kbb.y, d11);
            d00 = fma2(qq0[4], kc.x,  d00);  d01 = fma2(qq0[5], kc.y,  d01);
            d10 = fma2(qq1[4], kc.x,  d10);  d11 = fma2(qq1[5], kc.y,  d11);
            d00 = fma2(qq0[6], kd.x,  d00);  d01 = fma2(qq0[7], kd.y,  d01);
            d10 = fma2(qq1[6], kd.x,  d10);  d11 = fma2(qq1[7], kd.y,  d11);

            float2 s0 = unpk(add2(d00, d01));
            float2 s1 = unpk(add2(d10, d11));
            // logits are tiny by construction -> max-free softmax safe in fp32
            float p0 = __expf((s0.x + s0.y) * 0.25f);
            float p1 = __expf((s1.x + s1.y) * 0.25f);
            l0 += p0; l1 += p1;
            u64 pp0 = pk(p0, p0), pp1 = pk(p1, p1);

            const ulonglong2* vp = (const ulonglong2*)(vb_s + j*16);
            ulonglong2 va = vp[0], vb2 = vp[1], vc = vp[2], vd = vp[3];
            ac0[0] = fma2(pp0, va.x,  ac0[0]); ac0[1] = fma2(pp0, va.y,  ac0[1]);
            ac0[2] = fma2(pp0, vb2.x, ac0[2]); ac0[3] = fma2(pp0, vb2.y, ac0[3]);
            ac0[4] = fma2(pp0, vc.x,  ac0[4]); ac0[5] = fma2(pp0, vc.y,  ac0[5]);
            ac0[6] = fma2(pp0, vd.x,  ac0[6]); ac0[7] = fma2(pp0, vd.y,  ac0[7]);
            ac1[0] = fma2(pp1, va.x,  ac1[0]); ac1[1] = fma2(pp1, va.y,  ac1[1]);
            ac1[2] = fma2(pp1, vb2.x, ac1[2]); ac1[3] = fma2(pp1, vb2.y, ac1[3]);
            ac1[4] = fma2(pp1, vc.x,  ac1[4]); ac1[5] = fma2(pp1, vc.y,  ac1[5]);
            ac1[6] = fma2(pp1, vd.x,  ac1[6]); ac1[7] = fma2(pp1, vd.y,  ac1[7]);
        }
        __syncthreads();
    }

    // write per-oct partials
    {
        float* rp0 = red + (size_t)(oct*128 + lane)*17;
        float* rp1 = red + (size_t)(oct*128 + lane + 64)*17;
#pragma unroll
        for (int i = 0; i < 8; i++) {
            float2 u = unpk(ac0[i]); rp0[2*i] = u.x; rp0[2*i+1] = u.y;
            float2 v = unpk(ac1[i]); rp1[2*i] = v.x; rp1[2*i+1] = v.y;
        }
        rp0[16] = l0; rp1[16] = l1;
    }
    __syncthreads();

    // threads 0..127 reduce 8 octs and do epilogue for query qt*128+t
    if (t < 128) {
        float aa[16];
#pragma unroll
        for (int k = 0; k < 16; k++) aa[k] = 0.f;
        float l = 0.f;
#pragma unroll
        for (int o = 0; o < 8; o++) {
            const float* rp = red + (size_t)(o*128 + t)*17;
#pragma unroll
            for (int k = 0; k < 16; k++) aa[k] += rp[k];
            l += rp[16];
        }
        float inv = 1.0f / l;

        const int q = qt*128 + t;
        const float4* qp = (const float4*)(Qb + (size_t)q*16);
        float4 qa = qp[0], qb2 = qp[1], qc = qp[2], qd = qp[3];
        float qv[16] = { qa.x,qa.y,qa.z,qa.w, qb2.x,qb2.y,qb2.z,qb2.w,
                         qc.x,qc.y,qc.z,qc.w, qd.x,qd.y,qd.z,qd.w };
        const int b = bh >> 2, h = bh & 3;
        float* op = g_out + ((size_t)(b*Nn + q))*64 + h*16;
#pragma unroll
        for (int jj = 0; jj < 16; jj++) {
            float acc = 0.f;
#pragma unroll
            for (int ii = 0; ii < 16; ii++)
                acc = fmaf(qv[ii], ssec[ii][jj], acc);
            op[jj] = aa[jj] * inv * acc;
        }
    }
}

// ---------------- K4: out-proj + residual + LN2 + MLP + residual + transpose ----------------
__device__ __forceinline__ float leaky(float h) { return h > 0.f ? h : 0.01f * h; }

__global__ __launch_bounds__(64) void k_tail(
    const float* __restrict__ wout, const float* __restrict__ bout,
    const float* __restrict__ g2,   const float* __restrict__ be2,
    const float* __restrict__ w1,   const float* __restrict__ b1,
    const float* __restrict__ w2,   const float* __restrict__ b2,
    float* __restrict__ out)
{
    const int t = threadIdx.x;
    const int row0 = blockIdx.x * 4;
    __shared__ float so[4][64];
    __shared__ float sn[4][64];
    __shared__ float sh[4][256];
    __shared__ float sred[2][8];

#pragma unroll
    for (int r = 0; r < 4; r++) so[r][t] = g_out[(size_t)(row0+r)*64 + t];
    __syncthreads();

    float accP[4] = {0,0,0,0};
#pragma unroll 4
    for (int c = 0; c < 64; c++) {
        float w = wout[c*64 + t];
#pragma unroll
        for (int r = 0; r < 4; r++) accP[r] = fmaf(so[r][c], w, accP[r]);
    }
    const float bo = bout[t];
    float x2v[4];
#pragma unroll
    for (int r = 0; r < 4; r++)
        x2v[r] = g_xt[(size_t)(row0+r)*64 + t] + accP[r] + bo;

    const int wid = t >> 5, lane = t & 31;
#pragma unroll
    for (int r = 0; r < 4; r++) {
        float a = x2v[r], a2 = a*a;
#pragma unroll
        for (int o = 16; o > 0; o >>= 1) {
            a  += __shfl_xor_sync(0xffffffffu, a,  o);
            a2 += __shfl_xor_sync(0xffffffffu, a2, o);
        }
        if (lane == 0) { sred[wid][r*2] = a; sred[wid][r*2+1] = a2; }
    }
    __syncthreads();
    const float g2t = g2[t], be2t = be2[t];
#pragma unroll
    for (int r = 0; r < 4; r++) {
        float sxx = sred[0][r*2] + sred[1][r*2];
        float sq  = sred[0][r*2+1] + sred[1][r*2+1];
        float m = sxx*(1.f/64.f), v = sq*(1.f/64.f) - m*m;
        sn[r][t] = (x2v[r]-m)*rsqrtf(v + 1e-5f)*g2t + be2t;
    }
    __syncthreads();

    float h0[4], h1[4], h2[4], h3[4];
    const float bb0 = b1[t], bb1 = b1[t+64], bb2 = b1[t+128], bb3 = b1[t+192];
#pragma unroll
    for (int r = 0; r < 4; r++) { h0[r]=bb0; h1[r]=bb1; h2[r]=bb2; h3[r]=bb3; }
#pragma unroll 2
    for (int c = 0; c < 64; c++) {
        float w0 = w1[c*256 + t], w1v = w1[c*256 + t + 64];
        float w2v = w1[c*256 + t + 128], w3v = w1[c*256 + t + 192];
#pragma unroll
        for (int r = 0; r < 4; r++) {
            float xn = sn[r][c];
            h0[r] = fmaf(xn, w0,  h0[r]);
            h1[r] = fmaf(xn, w1v, h1[r]);
            h2[r] = fmaf(xn, w2v, h2[r]);
            h3[r] = fmaf(xn, w3v, h3[r]);
        }
    }
#pragma unroll
    for (int r = 0; r < 4; r++) {
        sh[r][t]       = leaky(h0[r]);
        sh[r][t + 64]  = leaky(h1[r]);
        sh[r][t + 128] = leaky(h2[r]);
        sh[r][t + 192] = leaky(h3[r]);
    }
    __syncthreads();

    float f[4] = {0,0,0,0};
#pragma unroll 2
    for (int j = 0; j < 256; j++) {
        float w = w2[j*64 + t];
#pragma unroll
        for (int r = 0; r < 4; r++) f[r] = fmaf(sh[r][j], w, f[r]);
    }
    const float b2t = b2[t];
#pragma unroll
    for (int r = 0; r < 4; r++) {
        int row = row0 + r;
        int b = row / Nn, nidx = row - b * Nn;
        out[((size_t)b*Cc + t)*Nn + nidx] = x2v[r] + f[r] + b2t;
    }
}

// ---------------- launch ----------------
extern "C" void kernel_launch(void* const* d_in, const int* in_sizes, int n_in,
                              void* d_out, int out_size)
{
    (void)in_sizes; (void)n_in; (void)out_size;
    const float* x    = (const float*)d_in[0];
    const float* y    = (const float*)d_in[1];
    const float* ln1g = (const float*)d_in[2];
    const float* ln1b = (const float*)d_in[3];
    const float* wsa1 = (const float*)d_in[4];
    const float* wsa2 = (const float*)d_in[5];
    const float* wse1 = (const float*)d_in[6];
    const float* wse2 = (const float*)d_in[7];
    const float* wout = (const float*)d_in[8];
    const float* bout = (const float*)d_in[9];
    const float* ln2g = (const float*)d_in[10];
    const float* ln2b = (const float*)d_in[11];
    const float* w1   = (const float*)d_in[12];
    const float* b1   = (const float*)d_in[13];
    const float* w2   = (const float*)d_in[14];
    const float* b2   = (const float*)d_in[15];
    float* out = (float*)d_out;

    cudaFuncSetAttribute(k_flash, cudaFuncAttributeMaxDynamicSharedMemorySize, FL_SMEM);

    k_ln_proj<<<Bb*Nn/4, 64>>>(x, y, ln1g, ln1b, wsa1, wsa2, wse1, wse2);
    dim3 gsec(NTILE, BH);
    k_secm_part<<<gsec, 256>>>();
    k_secm_soft<<<BH, 256>>>();
    dim3 gfl(NTILE, BH);
    k_flash<<<gfl, 512, FL_SMEM>>>();
    k_tail<<<Bb*Nn/4, 64>>>(wout, bout, ln2g, ln2b, w1, b1, w2, b2, out);
}

// round 3
// speedup vs baseline: 1.6444x; 1.5098x over previous
#include <cuda_runtime.h>
#include <cuda_bf16.h>
#include <cstdint>

#define Bb   2
#define Cc   64
#define Nn   2304
#define Hh   4
#define Dh   16
#define BH   (Bb*Hh)
#define MLP  256
#define NTILE 18            // Nn / 128

// flash-mma tiling
#define QT    64            // queries per block (4 warps x 16 rows)
#define KT    64            // keys per smem tile
#define KSPL  2             // key splits
#define KPB   (Nn/KSPL)     // 1152 keys per block
#define NTIL  (KPB/KT)      // 18 tiles
#define SKQ   24            // sK/sQ row stride (bf16) - conflict free
#define SVT   72            // sVt row stride (bf16) - conflict free

// ---------------- scratch (device globals; no allocation) ----------------
__device__ float g_xt [Bb*Nn*Cc];
__device__ float g_y1 [BH*Nn*Dh];
__device__ float g_y2 [BH*Nn*Dh];
__device__ float g_x1 [BH*Nn*Dh];
__device__ float g_x2 [BH*Nn*Dh];
__device__ float g_secp[BH*NTILE*256];
__device__ float g_secm[BH*256];
__device__ float g_out[Bb*Nn*Cc];
__device__ float g_po [KSPL*BH*Nn*16];   // unnormalized attention partials
__device__ float g_pl [KSPL*BH*Nn];      // partial row sums

// ---------------- helpers ----------------
__device__ __forceinline__ float ex2a(float x) {
    float r; asm("ex2.approx.f32 %0, %1;" : "=f"(r) : "f"(x)); return r;
}
__device__ __forceinline__ uint32_t cvt_bf2(float hi, float lo) {
    uint32_t r; asm("cvt.rn.bf16x2.f32 %0, %1, %2;" : "=r"(r) : "f"(hi), "f"(lo)); return r;
}
__device__ __forceinline__ void mma16816(float d[4],
    uint32_t a0, uint32_t a1, uint32_t a2, uint32_t a3,
    uint32_t b0, uint32_t b1)
{
    asm volatile("mma.sync.aligned.m16n8k16.row.col.f32.bf16.bf16.f32 "
        "{%0,%1,%2,%3}, {%4,%5,%6,%7}, {%8,%9}, {%0,%1,%2,%3};"
        : "+f"(d[0]), "+f"(d[1]), "+f"(d[2]), "+f"(d[3])
        : "r"(a0), "r"(a1), "r"(a2), "r"(a3), "r"(b0), "r"(b1));
}

// ---------------- K1: transpose + LayerNorm + 4 projections ----------------
__global__ __launch_bounds__(64) void k_ln_proj(
    const float* __restrict__ x, const float* __restrict__ y,
    const float* __restrict__ g, const float* __restrict__ be,
    const float* __restrict__ wsa1, const float* __restrict__ wsa2,
    const float* __restrict__ wse1, const float* __restrict__ wse2)
{
    const int t = threadIdx.x;
    const int row0 = blockIdx.x * 4;
    __shared__ float sxn[4][64], syn[4][64];
    __shared__ float sred[2][16];

    float xv[4], yv[4];
#pragma unroll
    for (int r = 0; r < 4; r++) {
        int row = row0 + r;
        int b = row / Nn, nidx = row - b * Nn;
        xv[r] = x[((size_t)b*Cc + t)*Nn + nidx];
        yv[r] = y[((size_t)b*Cc + t)*Nn + nidx];
        g_xt[(size_t)row*Cc + t] = xv[r];
    }
    const int wid = t >> 5, lane = t & 31;
#pragma unroll
    for (int r = 0; r < 4; r++) {
        float a = xv[r], a2 = a*a, bb = yv[r], b2v = bb*bb;
#pragma unroll
        for (int o = 16; o > 0; o >>= 1) {
            a   += __shfl_xor_sync(0xffffffffu, a,   o);
            a2  += __shfl_xor_sync(0xffffffffu, a2,  o);
            bb  += __shfl_xor_sync(0xffffffffu, bb,  o);
            b2v += __shfl_xor_sync(0xffffffffu, b2v, o);
        }
        if (lane == 0) {
            sred[wid][r*4+0] = a;  sred[wid][r*4+1] = a2;
            sred[wid][r*4+2] = bb; sred[wid][r*4+3] = b2v;
        }
    }
    __syncthreads();
    const float gt = g[t], bet = be[t];
#pragma unroll
    for (int r = 0; r < 4; r++) {
        float sx  = sred[0][r*4+0] + sred[1][r*4+0];
        float sx2 = sred[0][r*4+1] + sred[1][r*4+1];
        float sy  = sred[0][r*4+2] + sred[1][r*4+2];
        float sy2 = sred[0][r*4+3] + sred[1][r*4+3];
        float mx = sx*(1.f/64.f), vx = sx2*(1.f/64.f) - mx*mx;
        float my = sy*(1.f/64.f), vy = sy2*(1.f/64.f) - my*my;
        float rx = rsqrtf(vx + 1e-5f), ry = rsqrtf(vy + 1e-5f);
        sxn[r][t] = (xv[r]-mx)*rx*gt + bet;
        syn[r][t] = (yv[r]-my)*ry*gt + bet;
    }
    __syncthreads();

    float a1[4] = {0,0,0,0}, a2a[4] = {0,0,0,0}, a3[4] = {0,0,0,0}, a4[4] = {0,0,0,0};
#pragma unroll 4
    for (int c = 0; c < 64; c++) {
        float w1v = wsa1[c*64+t], w2v = wsa2[c*64+t];
        float w3v = wse1[c*64+t], w4v = wse2[c*64+t];
#pragma unroll
        for (int r = 0; r < 4; r++) {
            float yc = syn[r][c], xc = sxn[r][c];
            a1[r]  = fmaf(yc, w1v, a1[r]);
            a2a[r] = fmaf(yc, w2v, a2a[r]);
            a3[r]  = fmaf(xc, w3v, a3[r]);
            a4[r]  = fmaf(xc, w4v, a4[r]);
        }
    }
    const int h = t >> 4, d = t & 15;
#pragma unroll
    for (int r = 0; r < 4; r++) {
        int row = row0 + r;
        int b = row / Nn, nidx = row - b * Nn;
        size_t o = ((size_t)(b*Hh + h)*Nn + nidx)*Dh + d;
        g_y1[o] = a1[r]; g_y2[o] = a2a[r];
        g_x1[o] = a3[r]; g_x2[o] = a4[r];
    }
}

// ---------------- K2a: channel-attn logits, partial over n-tiles ----------------
__global__ __launch_bounds__(256) void k_secm_part()
{
    const int bh = blockIdx.y, nb = blockIdx.x;
    const int t = threadIdx.x, i = t >> 4, j = t & 15;
    const float* __restrict__ x1 = g_x1 + (size_t)bh*Nn*Dh;
    const float* __restrict__ x2 = g_x2 + (size_t)bh*Nn*Dh;
    const int n0 = nb * 128;
    float s = 0.f;
#pragma unroll 4
    for (int n = n0; n < n0 + 128; n++)
        s = fmaf(x1[n*16 + i], x2[n*16 + j], s);
    g_secp[((size_t)bh*NTILE + nb)*256 + t] = s;
}

// ---------------- K2b: reduce partials + softmax (16x16 per bh) ----------------
__global__ __launch_bounds__(256) void k_secm_soft()
{
    const int bh = blockIdx.x;
    const int t = threadIdx.x, i = t >> 4;
    float s = 0.f;
#pragma unroll
    for (int k = 0; k < NTILE; k++)
        s += g_secp[((size_t)bh*NTILE + k)*256 + t];
    s *= (0.25f / 144.0f);
    __shared__ float sm[16][16], se[16][16];
    sm[i][t & 15] = s;
    __syncthreads();
    float rmax = -1e30f;
#pragma unroll
    for (int k = 0; k < 16; k++) rmax = fmaxf(rmax, sm[i][k]);
    float e = __expf(s - rmax);
    se[i][t & 15] = e;
    __syncthreads();
    float rs = 0.f;
#pragma unroll
    for (int k = 0; k < 16; k++) rs += se[i][k];
    g_secm[bh*256 + t] = e / rs;
}

// ---------------- K3: flash attention via bf16 mma.sync (FA2 style) ----------------
// grid (Nn/QT=36, BH, KSPL), 128 threads = 4 warps, 16 query rows per warp.
__global__ __launch_bounds__(128) void k_flash_mma()
{
    const int qt = blockIdx.x, bh = blockIdx.y, ks = blockIdx.z;
    const int t = threadIdx.x, wid = t >> 5, lane = t & 31;
    const int g = lane >> 2, tg = lane & 3;

    __shared__ __align__(16) __nv_bfloat16 sQ [QT*SKQ];
    __shared__ __align__(16) __nv_bfloat16 sK [KT*SKQ];
    __shared__ __align__(16) __nv_bfloat16 sVt[16*SVT];

    const float* __restrict__ Qb = g_y1 + (size_t)bh*Nn*Dh;
    const float* __restrict__ Kb = g_y2 + (size_t)bh*Nn*Dh;
    const float* __restrict__ Vb = g_x1 + (size_t)bh*Nn*Dh;

    // Q tile -> bf16 smem (rows stride SKQ)
    {
        const float4* src = (const float4*)(Qb + (size_t)qt*QT*16);
#pragma unroll
        for (int i = t; i < QT*4; i += 128) {
            float4 v = src[i];
            int key = i >> 2, dq = (i & 3) * 4;
            __nv_bfloat16* d = sQ + key*SKQ + dq;
            d[0] = __float2bfloat16(v.x); d[1] = __float2bfloat16(v.y);
            d[2] = __float2bfloat16(v.z); d[3] = __float2bfloat16(v.w);
        }
    }
    __syncthreads();

    // per-warp Q A-fragment (rows wid*16 .. +15), reused all tiles
    const int qr = wid * 16;
    uint32_t qa0 = *(const uint32_t*)(sQ + (qr+g  )*SKQ + 2*tg);
    uint32_t qa1 = *(const uint32_t*)(sQ + (qr+g+8)*SKQ + 2*tg);
    uint32_t qa2 = *(const uint32_t*)(sQ + (qr+g  )*SKQ + 2*tg + 8);
    uint32_t qa3 = *(const uint32_t*)(sQ + (qr+g+8)*SKQ + 2*tg + 8);

    float o[2][4] = {{0,0,0,0},{0,0,0,0}};
    float lsum_lo = 0.f, lsum_hi = 0.f;
    const float SC = 0.25f * 1.4426950408889634f;   // scale * log2(e)

    for (int kt = 0; kt < NTIL; kt++) {
        const int key0 = ks*KPB + kt*KT;
        __syncthreads();
        {
            const float4* srcK = (const float4*)(Kb + (size_t)key0*16);
            const float4* srcV = (const float4*)(Vb + (size_t)key0*16);
#pragma unroll
            for (int i = t; i < KT*4; i += 128) {
                float4 kv = srcK[i];
                int key = i >> 2, dq = (i & 3) * 4;
                __nv_bfloat16* d = sK + key*SKQ + dq;
                d[0] = __float2bfloat16(kv.x); d[1] = __float2bfloat16(kv.y);
                d[2] = __float2bfloat16(kv.z); d[3] = __float2bfloat16(kv.w);
                float4 vv = srcV[i];
                sVt[(dq+0)*SVT + key] = __float2bfloat16(vv.x);
                sVt[(dq+1)*SVT + key] = __float2bfloat16(vv.y);
                sVt[(dq+2)*SVT + key] = __float2bfloat16(vv.z);
                sVt[(dq+3)*SVT + key] = __float2bfloat16(vv.w);
            }
        }
        __syncthreads();

        // S = Q K^T  (16 x 64), 8 n-tiles of 8 keys
        float s[8][4];
        uint32_t p[8][2];
#pragma unroll
        for (int n = 0; n < 8; n++) {
            s[n][0] = s[n][1] = s[n][2] = s[n][3] = 0.f;
            uint32_t b0 = *(const uint32_t*)(sK + (n*8+g)*SKQ + 2*tg);
            uint32_t b1 = *(const uint32_t*)(sK + (n*8+g)*SKQ + 2*tg + 8);
            mma16816(s[n], qa0, qa1, qa2, qa3, b0, b1);
        }
        // exp (max-free: logits tiny by construction) + pack to bf16 P frags
#pragma unroll
        for (int n = 0; n < 8; n++) {
            float e0 = ex2a(s[n][0]*SC), e1 = ex2a(s[n][1]*SC);
            float e2 = ex2a(s[n][2]*SC), e3 = ex2a(s[n][3]*SC);
            lsum_lo += e0 + e1;  lsum_hi += e2 + e3;
            p[n][0] = cvt_bf2(e1, e0);   // low = col 2tg
            p[n][1] = cvt_bf2(e3, e2);
        }
        // O += P V  (4 k-tiles of 16 keys, 2 n-tiles of 8 dims)
#pragma unroll
        for (int kk = 0; kk < 4; kk++) {
            uint32_t a0 = p[2*kk][0],   a1 = p[2*kk][1];
            uint32_t a2 = p[2*kk+1][0], a3 = p[2*kk+1][1];
#pragma unroll
            for (int n = 0; n < 2; n++) {
                uint32_t b0 = *(const uint32_t*)(sVt + (n*8+g)*SVT + kk*16 + 2*tg);
                uint32_t b1 = *(const uint32_t*)(sVt + (n*8+g)*SVT + kk*16 + 2*tg + 8);
                mma16816(o[n], a0, a1, a2, a3, b0, b1);
            }
        }
    }

    // reduce row sums across the 4 lanes of each group
    lsum_lo += __shfl_xor_sync(0xffffffffu, lsum_lo, 1);
    lsum_lo += __shfl_xor_sync(0xffffffffu, lsum_lo, 2);
    lsum_hi += __shfl_xor_sync(0xffffffffu, lsum_hi, 1);
    lsum_hi += __shfl_xor_sync(0xffffffffu, lsum_hi, 2);

    // write partials
    const int q_lo = qt*QT + qr + g;
    const int q_hi = q_lo + 8;
    float* po = g_po + ((size_t)(ks*BH + bh)*Nn)*16;
#pragma unroll
    for (int n = 0; n < 2; n++) {
        po[(size_t)q_lo*16 + n*8 + 2*tg    ] = o[n][0];
        po[(size_t)q_lo*16 + n*8 + 2*tg + 1] = o[n][1];
        po[(size_t)q_hi*16 + n*8 + 2*tg    ] = o[n][2];
        po[(size_t)q_hi*16 + n*8 + 2*tg + 1] = o[n][3];
    }
    if (tg == 0) {
        g_pl[(size_t)(ks*BH + bh)*Nn + q_lo] = lsum_lo;
        g_pl[(size_t)(ks*BH + bh)*Nn + q_hi] = lsum_hi;
    }
}

// ---------------- K3b: combine key-splits + channel-map epilogue ----------------
__global__ __launch_bounds__(128) void k_comb()
{
    const int bh = blockIdx.y, qb = blockIdx.x, t = threadIdx.x;
    __shared__ float ssec[16][16];
    for (int i = t; i < 256; i += 128) ssec[i >> 4][i & 15] = g_secm[bh*256 + i];
    __syncthreads();

    const int q = qb*128 + t;
    float l = g_pl[(size_t)bh*Nn + q] + g_pl[(size_t)(BH + bh)*Nn + q];
    float inv = 1.0f / l;

    const float* Qr = g_y1 + ((size_t)bh*Nn + q)*16;
    float qv[16];
#pragma unroll
    for (int i = 0; i < 16; i++) qv[i] = Qr[i];

    const float* p0 = g_po + ((size_t)bh*Nn + q)*16;
    const float* p1 = g_po + ((size_t)(BH + bh)*Nn + q)*16;
    const int b = bh >> 2, h = bh & 3;
    float* op = g_out + ((size_t)(b*Nn + q))*64 + h*16;
#pragma unroll
    for (int c = 0; c < 16; c++) {
        float o1 = (p0[c] + p1[c]) * inv;
        float acc = 0.f;
#pragma unroll
        for (int i = 0; i < 16; i++) acc = fmaf(qv[i], ssec[i][c], acc);
        op[c] = o1 * acc;
    }
}

// ---------------- K4: out-proj + residual + LN2 + MLP + residual + transpose ----------------
__device__ __forceinline__ float leaky(float h) { return h > 0.f ? h : 0.01f * h; }

__global__ __launch_bounds__(64) void k_tail(
    const float* __restrict__ wout, const float* __restrict__ bout,
    const float* __restrict__ g2,   const float* __restrict__ be2,
    const float* __restrict__ w1,   const float* __restrict__ b1,
    const float* __restrict__ w2,   const float* __restrict__ b2,
    float* __restrict__ out)
{
    const int t = threadIdx.x;
    const int row0 = blockIdx.x * 4;
    __shared__ float so[4][64];
    __shared__ float sn[4][64];
    __shared__ float sh[4][256];
    __shared__ float sred[2][8];

#pragma unroll
    for (int r = 0; r < 4; r++) so[r][t] = g_out[(size_t)(row0+r)*64 + t];
    __syncthreads();

    float accP[4] = {0,0,0,0};
#pragma unroll 4
    for (int c = 0; c < 64; c++) {
        float w = wout[c*64 + t];
#pragma unroll
        for (int r = 0; r < 4; r++) accP[r] = fmaf(so[r][c], w, accP[r]);
    }
    const float bo = bout[t];
    float x2v[4];
#pragma unroll
    for (int r = 0; r < 4; r++)
        x2v[r] = g_xt[(size_t)(row0+r)*64 + t] + accP[r] + bo;

    const int wid = t >> 5, lane = t & 31;
#pragma unroll
    for (int r = 0; r < 4; r++) {
        float a = x2v[r], a2 = a*a;
#pragma unroll
        for (int o = 16; o > 0; o >>= 1) {
            a  += __shfl_xor_sync(0xffffffffu, a,  o);
            a2 += __shfl_xor_sync(0xffffffffu, a2, o);
        }
        if (lane == 0) { sred[wid][r*2] = a; sred[wid][r*2+1] = a2; }
    }
    __syncthreads();
    const float g2t = g2[t], be2t = be2[t];
#pragma unroll
    for (int r = 0; r < 4; r++) {
        float sxx = sred[0][r*2] + sred[1][r*2];
        float sq  = sred[0][r*2+1] + sred[1][r*2+1];
        float m = sxx*(1.f/64.f), v = sq*(1.f/64.f) - m*m;
        sn[r][t] = (x2v[r]-m)*rsqrtf(v + 1e-5f)*g2t + be2t;
    }
    __syncthreads();

    float h0[4], h1[4], h2[4], h3[4];
    const float bb0 = b1[t], bb1 = b1[t+64], bb2 = b1[t+128], bb3 = b1[t+192];
#pragma unroll
    for (int r = 0; r < 4; r++) { h0[r]=bb0; h1[r]=bb1; h2[r]=bb2; h3[r]=bb3; }
#pragma unroll 2
    for (int c = 0; c < 64; c++) {
        float w0 = w1[c*256 + t], w1v = w1[c*256 + t + 64];
        float w2v = w1[c*256 + t + 128], w3v = w1[c*256 + t + 192];
#pragma unroll
        for (int r = 0; r < 4; r++) {
            float xn = sn[r][c];
            h0[r] = fmaf(xn, w0,  h0[r]);
            h1[r] = fmaf(xn, w1v, h1[r]);
            h2[r] = fmaf(xn, w2v, h2[r]);
            h3[r] = fmaf(xn, w3v, h3[r]);
        }
    }
#pragma unroll
    for (int r = 0; r < 4; r++) {
        sh[r][t]       = leaky(h0[r]);
        sh[r][t + 64]  = leaky(h1[r]);
        sh[r][t + 128] = leaky(h2[r]);
        sh[r][t + 192] = leaky(h3[r]);
    }
    __syncthreads();

    float f[4] = {0,0,0,0};
#pragma unroll 2
    for (int j = 0; j < 256; j++) {
        float w = w2[j*64 + t];
#pragma unroll
        for (int r = 0; r < 4; r++) f[r] = fmaf(sh[r][j], w, f[r]);
    }
    const float b2t = b2[t];
#pragma unroll
    for (int r = 0; r < 4; r++) {
        int row = row0 + r;
        int b = row / Nn, nidx = row - b * Nn;
        out[((size_t)b*Cc + t)*Nn + nidx] = x2v[r] + f[r] + b2t;
    }
}

// ---------------- launch ----------------
extern "C" void kernel_launch(void* const* d_in, const int* in_sizes, int n_in,
                              void* d_out, int out_size)
{
    (void)in_sizes; (void)n_in; (void)out_size;
    const float* x    = (const float*)d_in[0];
    const float* y    = (const float*)d_in[1];
    const float* ln1g = (const float*)d_in[2];
    const float* ln1b = (const float*)d_in[3];
    const float* wsa1 = (const float*)d_in[4];
    const float* wsa2 = (const float*)d_in[5];
    const float* wse1 = (const float*)d_in[6];
    const float* wse2 = (const float*)d_in[7];
    const float* wout = (const float*)d_in[8];
    const float* bout = (const float*)d_in[9];
    const float* ln2g = (const float*)d_in[10];
    const float* ln2b = (const float*)d_in[11];
    const float* w1   = (const float*)d_in[12];
    const float* b1   = (const float*)d_in[13];
    const float* w2   = (const float*)d_in[14];
    const float* b2   = (const float*)d_in[15];
    float* out = (float*)d_out;

    k_ln_proj<<<Bb*Nn/4, 64>>>(x, y, ln1g, ln1b, wsa1, wsa2, wse1, wse2);
    dim3 gsec(NTILE, BH);
    k_secm_part<<<gsec, 256>>>();
    k_secm_soft<<<BH, 256>>>();
    dim3 gfl(Nn/QT, BH, KSPL);
    k_flash_mma<<<gfl, 128>>>();
    dim3 gcmb(Nn/128, BH);
    k_comb<<<gcmb, 128>>>();
    k_tail<<<Bb*Nn/4, 64>>>(wout, bout, ln2g, ln2b, w1, b1, w2, b2, out);
}

// round 4
// speedup vs baseline: 1.8308x; 1.1134x over previous
#include <cuda_runtime.h>
#include <cuda_bf16.h>
#include <cstdint>

#define Bb   2
#define Cc   64
#define Nn   2304
#define Hh   4
#define Dh   16
#define BH   (Bb*Hh)
#define MLP  256
#define NTILE 18            // Nn / 128

// flash-mma tiling
#define QT    64            // queries per block (4 warps x 16 rows)
#define KT    64            // keys per smem tile
#define KSPL  4             // key splits
#define KPB   (Nn/KSPL)     // 576 keys per block
#define NTIL  (KPB/KT)      // 9 tiles
#define SKQ   24            // sK/sQ row stride (bf16) - conflict free
#define SVT   72            // sVt row stride (bf16) - conflict free

typedef unsigned long long u64;

// ---------------- scratch (device globals; no allocation) ----------------
__device__ float g_xt [Bb*Nn*Cc];
__device__ float g_y1 [BH*Nn*Dh];
__device__ float g_y2 [BH*Nn*Dh];
__device__ float g_x1 [BH*Nn*Dh];
__device__ float g_x2 [BH*Nn*Dh];
__device__ float g_secp[BH*NTILE*256];
__device__ float g_out[Bb*Nn*Cc];
__device__ float g_po [KSPL*BH*Nn*16];   // unnormalized attention partials
__device__ float g_pl [KSPL*BH*Nn];      // partial row sums

// ---------------- helpers ----------------
__device__ __forceinline__ float ex2a(float x) {
    float r; asm("ex2.approx.f32 %0, %1;" : "=f"(r) : "f"(x)); return r;
}
__device__ __forceinline__ uint32_t cvt_bf2(float hi, float lo) {
    uint32_t r; asm("cvt.rn.bf16x2.f32 %0, %1, %2;" : "=r"(r) : "f"(hi), "f"(lo)); return r;
}
__device__ __forceinline__ void mma16816(float d[4],
    uint32_t a0, uint32_t a1, uint32_t a2, uint32_t a3,
    uint32_t b0, uint32_t b1)
{
    asm volatile("mma.sync.aligned.m16n8k16.row.col.f32.bf16.bf16.f32 "
        "{%0,%1,%2,%3}, {%4,%5,%6,%7}, {%8,%9}, {%0,%1,%2,%3};"
        : "+f"(d[0]), "+f"(d[1]), "+f"(d[2]), "+f"(d[3])
        : "r"(a0), "r"(a1), "r"(a2), "r"(a3), "r"(b0), "r"(b1));
}
__device__ __forceinline__ u64 fma2(u64 a, u64 b, u64 c) {
    u64 d; asm("fma.rn.f32x2 %0, %1, %2, %3;" : "=l"(d) : "l"(a), "l"(b), "l"(c)); return d;
}
__device__ __forceinline__ float2 unpk(u64 v) {
    float2 r; asm("mov.b64 {%0,%1}, %2;" : "=f"(r.x), "=f"(r.y) : "l"(v)); return r;
}
__device__ __forceinline__ u64 pk(float lo, float hi) {
    u64 v; asm("mov.b64 %0, {%1,%2};" : "=l"(v) : "f"(lo), "f"(hi)); return v;
}

// ---------------- K1: transpose + LayerNorm + 4 projections ----------------
__global__ __launch_bounds__(64) void k_ln_proj(
    const float* __restrict__ x, const float* __restrict__ y,
    const float* __restrict__ g, const float* __restrict__ be,
    const float* __restrict__ wsa1, const float* __restrict__ wsa2,
    const float* __restrict__ wse1, const float* __restrict__ wse2)
{
    const int t = threadIdx.x;
    const int row0 = blockIdx.x * 4;
    __shared__ float sxn[4][64], syn[4][64];
    __shared__ float sred[2][16];

    float xv[4], yv[4];
#pragma unroll
    for (int r = 0; r < 4; r++) {
        int row = row0 + r;
        int b = row / Nn, nidx = row - b * Nn;
        xv[r] = x[((size_t)b*Cc + t)*Nn + nidx];
        yv[r] = y[((size_t)b*Cc + t)*Nn + nidx];
        g_xt[(size_t)row*Cc + t] = xv[r];
    }
    const int wid = t >> 5, lane = t & 31;
#pragma unroll
    for (int r = 0; r < 4; r++) {
        float a = xv[r], a2 = a*a, bb = yv[r], b2v = bb*bb;
#pragma unroll
        for (int o = 16; o > 0; o >>= 1) {
            a   += __shfl_xor_sync(0xffffffffu, a,   o);
            a2  += __shfl_xor_sync(0xffffffffu, a2,  o);
            bb  += __shfl_xor_sync(0xffffffffu, bb,  o);
            b2v += __shfl_xor_sync(0xffffffffu, b2v, o);
        }
        if (lane == 0) {
            sred[wid][r*4+0] = a;  sred[wid][r*4+1] = a2;
            sred[wid][r*4+2] = bb; sred[wid][r*4+3] = b2v;
        }
    }
    __syncthreads();
    const float gt = g[t], bet = be[t];
#pragma unroll
    for (int r = 0; r < 4; r++) {
        float sx  = sred[0][r*4+0] + sred[1][r*4+0];
        float sx2 = sred[0][r*4+1] + sred[1][r*4+1];
        float sy  = sred[0][r*4+2] + sred[1][r*4+2];
        float sy2 = sred[0][r*4+3] + sred[1][r*4+3];
        float mx = sx*(1.f/64.f), vx = sx2*(1.f/64.f) - mx*mx;
        float my = sy*(1.f/64.f), vy = sy2*(1.f/64.f) - my*my;
        float rx = rsqrtf(vx + 1e-5f), ry = rsqrtf(vy + 1e-5f);
        sxn[r][t] = (xv[r]-mx)*rx*gt + bet;
        syn[r][t] = (yv[r]-my)*ry*gt + bet;
    }
    __syncthreads();

    float a1[4] = {0,0,0,0}, a2a[4] = {0,0,0,0}, a3[4] = {0,0,0,0}, a4[4] = {0,0,0,0};
#pragma unroll 4
    for (int c = 0; c < 64; c++) {
        float w1v = wsa1[c*64+t], w2v = wsa2[c*64+t];
        float w3v = wse1[c*64+t], w4v = wse2[c*64+t];
#pragma unroll
        for (int r = 0; r < 4; r++) {
            float yc = syn[r][c], xc = sxn[r][c];
            a1[r]  = fmaf(yc, w1v, a1[r]);
            a2a[r] = fmaf(yc, w2v, a2a[r]);
            a3[r]  = fmaf(xc, w3v, a3[r]);
            a4[r]  = fmaf(xc, w4v, a4[r]);
        }
    }
    const int h = t >> 4, d = t & 15;
#pragma unroll
    for (int r = 0; r < 4; r++) {
        int row = row0 + r;
        int b = row / Nn, nidx = row - b * Nn;
        size_t o = ((size_t)(b*Hh + h)*Nn + nidx)*Dh + d;
        g_y1[o] = a1[r]; g_y2[o] = a2a[r];
        g_x1[o] = a3[r]; g_x2[o] = a4[r];
    }
}

// ---------------- K2a: channel-attn logits, partial over n-tiles ----------------
__global__ __launch_bounds__(256) void k_secm_part()
{
    const int bh = blockIdx.y, nb = blockIdx.x;
    const int t = threadIdx.x, i = t >> 4, j = t & 15;
    const float* __restrict__ x1 = g_x1 + (size_t)bh*Nn*Dh;
    const float* __restrict__ x2 = g_x2 + (size_t)bh*Nn*Dh;
    const int n0 = nb * 128;
    float s = 0.f;
#pragma unroll 4
    for (int n = n0; n < n0 + 128; n++)
        s = fmaf(x1[n*16 + i], x2[n*16 + j], s);
    g_secp[((size_t)bh*NTILE + nb)*256 + t] = s;
}

// ---------------- K3: flash attention via bf16 mma.sync (FA2 style) ----------------
// grid (Nn/QT=36, BH, KSPL), 128 threads = 4 warps, 16 query rows per warp.
__global__ __launch_bounds__(128) void k_flash_mma()
{
    const int qt = blockIdx.x, bh = blockIdx.y, ks = blockIdx.z;
    const int t = threadIdx.x, wid = t >> 5, lane = t & 31;
    const int g = lane >> 2, tg = lane & 3;

    __shared__ __align__(16) __nv_bfloat16 sQ [QT*SKQ];
    __shared__ __align__(16) __nv_bfloat16 sK [KT*SKQ];
    __shared__ __align__(16) __nv_bfloat16 sVt[16*SVT];

    const float* __restrict__ Qb = g_y1 + (size_t)bh*Nn*Dh;
    const float* __restrict__ Kb = g_y2 + (size_t)bh*Nn*Dh;
    const float* __restrict__ Vb = g_x1 + (size_t)bh*Nn*Dh;

    // Q tile -> bf16 smem (rows stride SKQ)
    {
        const float4* src = (const float4*)(Qb + (size_t)qt*QT*16);
#pragma unroll
        for (int i = t; i < QT*4; i += 128) {
            float4 v = src[i];
            int key = i >> 2, dq = (i & 3) * 4;
            __nv_bfloat16* d = sQ + key*SKQ + dq;
            d[0] = __float2bfloat16(v.x); d[1] = __float2bfloat16(v.y);
            d[2] = __float2bfloat16(v.z); d[3] = __float2bfloat16(v.w);
        }
    }
    __syncthreads();

    // per-warp Q A-fragment (rows wid*16 .. +15), reused all tiles
    const int qr = wid * 16;
    uint32_t qa0 = *(const uint32_t*)(sQ + (qr+g  )*SKQ + 2*tg);
    uint32_t qa1 = *(const uint32_t*)(sQ + (qr+g+8)*SKQ + 2*tg);
    uint32_t qa2 = *(const uint32_t*)(sQ + (qr+g  )*SKQ + 2*tg + 8);
    uint32_t qa3 = *(const uint32_t*)(sQ + (qr+g+8)*SKQ + 2*tg + 8);

    float o[2][4] = {{0,0,0,0},{0,0,0,0}};
    float lsum_lo = 0.f, lsum_hi = 0.f;
    const float SC = 0.25f * 1.4426950408889634f;   // scale * log2(e)

    for (int kt = 0; kt < NTIL; kt++) {
        const int key0 = ks*KPB + kt*KT;
        __syncthreads();
        {
            const float4* srcK = (const float4*)(Kb + (size_t)key0*16);
            const float4* srcV = (const float4*)(Vb + (size_t)key0*16);
#pragma unroll
            for (int i = t; i < KT*4; i += 128) {
                float4 kv = srcK[i];
                int key = i >> 2, dq = (i & 3) * 4;
                __nv_bfloat16* d = sK + key*SKQ + dq;
                d[0] = __float2bfloat16(kv.x); d[1] = __float2bfloat16(kv.y);
                d[2] = __float2bfloat16(kv.z); d[3] = __float2bfloat16(kv.w);
                float4 vv = srcV[i];
                sVt[(dq+0)*SVT + key] = __float2bfloat16(vv.x);
                sVt[(dq+1)*SVT + key] = __float2bfloat16(vv.y);
                sVt[(dq+2)*SVT + key] = __float2bfloat16(vv.z);
                sVt[(dq+3)*SVT + key] = __float2bfloat16(vv.w);
            }
        }
        __syncthreads();

        // S = Q K^T  (16 x 64), 8 n-tiles of 8 keys
        float s[8][4];
        uint32_t p[8][2];
#pragma unroll
        for (int n = 0; n < 8; n++) {
            s[n][0] = s[n][1] = s[n][2] = s[n][3] = 0.f;
            uint32_t b0 = *(const uint32_t*)(sK + (n*8+g)*SKQ + 2*tg);
            uint32_t b1 = *(const uint32_t*)(sK + (n*8+g)*SKQ + 2*tg + 8);
            mma16816(s[n], qa0, qa1, qa2, qa3, b0, b1);
        }
        // exp (max-free: logits tiny by construction) + pack to bf16 P frags
#pragma unroll
        for (int n = 0; n < 8; n++) {
            float e0 = ex2a(s[n][0]*SC), e1 = ex2a(s[n][1]*SC);
            float e2 = ex2a(s[n][2]*SC), e3 = ex2a(s[n][3]*SC);
            lsum_lo += e0 + e1;  lsum_hi += e2 + e3;
            p[n][0] = cvt_bf2(e1, e0);   // low = col 2tg
            p[n][1] = cvt_bf2(e3, e2);
        }
        // O += P V  (4 k-tiles of 16 keys, 2 n-tiles of 8 dims)
#pragma unroll
        for (int kk = 0; kk < 4; kk++) {
            uint32_t a0 = p[2*kk][0],   a1 = p[2*kk][1];
            uint32_t a2 = p[2*kk+1][0], a3 = p[2*kk+1][1];
#pragma unroll
            for (int n = 0; n < 2; n++) {
                uint32_t b0 = *(const uint32_t*)(sVt + (n*8+g)*SVT + kk*16 + 2*tg);
                uint32_t b1 = *(const uint32_t*)(sVt + (n*8+g)*SVT + kk*16 + 2*tg + 8);
                mma16816(o[n], a0, a1, a2, a3, b0, b1);
            }
        }
    }

    // reduce row sums across the 4 lanes of each group
    lsum_lo += __shfl_xor_sync(0xffffffffu, lsum_lo, 1);
    lsum_lo += __shfl_xor_sync(0xffffffffu, lsum_lo, 2);
    lsum_hi += __shfl_xor_sync(0xffffffffu, lsum_hi, 1);
    lsum_hi += __shfl_xor_sync(0xffffffffu, lsum_hi, 2);

    // write partials
    const int q_lo = qt*QT + qr + g;
    const int q_hi = q_lo + 8;
    float* po = g_po + ((size_t)(ks*BH + bh)*Nn)*16;
#pragma unroll
    for (int n = 0; n < 2; n++) {
        po[(size_t)q_lo*16 + n*8 + 2*tg    ] = o[n][0];
        po[(size_t)q_lo*16 + n*8 + 2*tg + 1] = o[n][1];
        po[(size_t)q_hi*16 + n*8 + 2*tg    ] = o[n][2];
        po[(size_t)q_hi*16 + n*8 + 2*tg + 1] = o[n][3];
    }
    if (tg == 0) {
        g_pl[(size_t)(ks*BH + bh)*Nn + q_lo] = lsum_lo;
        g_pl[(size_t)(ks*BH + bh)*Nn + q_hi] = lsum_hi;
    }
}

// ---------------- K3b: combine key-splits + channel softmax + epilogue ----------------
__global__ __launch_bounds__(256) void k_comb()
{
    const int bh = blockIdx.y, qb = blockIdx.x, t = threadIdx.x;
    __shared__ float ssec[16][16];
    __shared__ float sm[16][16], se[16][16];

    // recompute channel softmax from partials (cheap, removes a kernel)
    {
        float s = 0.f;
#pragma unroll
        for (int k = 0; k < NTILE; k++)
            s += g_secp[((size_t)bh*NTILE + k)*256 + t];
        s *= (0.25f / 144.0f);
        const int i = t >> 4, j = t & 15;
        sm[i][j] = s;
        __syncthreads();
        float rmax = -1e30f;
#pragma unroll
        for (int k = 0; k < 16; k++) rmax = fmaxf(rmax, sm[i][k]);
        float e = __expf(s - rmax);
        se[i][j] = e;
        __syncthreads();
        float rs = 0.f;
#pragma unroll
        for (int k = 0; k < 16; k++) rs += se[i][k];
        ssec[i][j] = e / rs;
        __syncthreads();
    }

    const int q = qb*256 + t;
    float l = 0.f;
#pragma unroll
    for (int ks = 0; ks < KSPL; ks++)
        l += g_pl[(size_t)(ks*BH + bh)*Nn + q];
    float inv = 1.0f / l;

    const float* Qr = g_y1 + ((size_t)bh*Nn + q)*16;
    float qv[16];
#pragma unroll
    for (int i = 0; i < 16; i++) qv[i] = Qr[i];

    float pv[16];
#pragma unroll
    for (int c = 0; c < 16; c++) pv[c] = 0.f;
#pragma unroll
    for (int ks = 0; ks < KSPL; ks++) {
        const float* p = g_po + ((size_t)(ks*BH + bh)*Nn + q)*16;
#pragma unroll
        for (int c = 0; c < 16; c++) pv[c] += p[c];
    }

    const int b = bh >> 2, h = bh & 3;
    float* op = g_out + ((size_t)(b*Nn + q))*64 + h*16;
#pragma unroll
    for (int c = 0; c < 16; c++) {
        float acc = 0.f;
#pragma unroll
        for (int i = 0; i < 16; i++) acc = fmaf(qv[i], ssec[i][c], acc);
        op[c] = pv[c] * inv * acc;
    }
}

// ---------------- K4: out-proj + residual + LN2 + MLP + residual (f32x2) ----------------
__device__ __forceinline__ float leaky(float h) { return h > 0.f ? h : 0.01f * h; }

__global__ __launch_bounds__(64) void k_tail(
    const float* __restrict__ wout, const float* __restrict__ bout,
    const float* __restrict__ g2,   const float* __restrict__ be2,
    const float* __restrict__ w1,   const float* __restrict__ b1,
    const float* __restrict__ w2,   const float* __restrict__ b2,
    float* __restrict__ out)
{
    const int t = threadIdx.x;
    const int row0 = blockIdx.x * 4;
    __shared__ u64 sop[2][64];   // attn-out rows packed (0,1),(2,3)
    __shared__ u64 snp[2][64];   // normalized rows packed
    __shared__ u64 shp[2][256];  // hidden rows packed
    __shared__ float sred[2][8];

    {
        float s0 = g_out[(size_t)(row0+0)*64 + t];
        float s1 = g_out[(size_t)(row0+1)*64 + t];
        float s2 = g_out[(size_t)(row0+2)*64 + t];
        float s3 = g_out[(size_t)(row0+3)*64 + t];
        sop[0][t] = pk(s0, s1);
        sop[1][t] = pk(s2, s3);
    }
    __syncthreads();

    u64 ac[2] = {0ull, 0ull};
#pragma unroll 4
    for (int c = 0; c < 64; c++) {
        float w = wout[c*64 + t];
        u64 ww = pk(w, w);
        ac[0] = fma2(ww, sop[0][c], ac[0]);
        ac[1] = fma2(ww, sop[1][c], ac[1]);
    }
    const float bo = bout[t];
    float2 a01 = unpk(ac[0]), a23 = unpk(ac[1]);
    float x2v[4];
    x2v[0] = g_xt[(size_t)(row0+0)*64 + t] + a01.x + bo;
    x2v[1] = g_xt[(size_t)(row0+1)*64 + t] + a01.y + bo;
    x2v[2] = g_xt[(size_t)(row0+2)*64 + t] + a23.x + bo;
    x2v[3] = g_xt[(size_t)(row0+3)*64 + t] + a23.y + bo;

    const int wid = t >> 5, lane = t & 31;
#pragma unroll
    for (int r = 0; r < 4; r++) {
        float a = x2v[r], a2 = a*a;
#pragma unroll
        for (int o = 16; o > 0; o >>= 1) {
            a  += __shfl_xor_sync(0xffffffffu, a,  o);
            a2 += __shfl_xor_sync(0xffffffffu, a2, o);
        }
        if (lane == 0) { sred[wid][r*2] = a; sred[wid][r*2+1] = a2; }
    }
    __syncthreads();
    const float g2t = g2[t], be2t = be2[t];
    float snv[4];
#pragma unroll
    for (int r = 0; r < 4; r++) {
        float sxx = sred[0][r*2] + sred[1][r*2];
        float sq  = sred[0][r*2+1] + sred[1][r*2+1];
        float m = sxx*(1.f/64.f), v = sq*(1.f/64.f) - m*m;
        snv[r] = (x2v[r]-m)*rsqrtf(v + 1e-5f)*g2t + be2t;
    }
    snp[0][t] = pk(snv[0], snv[1]);
    snp[1][t] = pk(snv[2], snv[3]);
    __syncthreads();

    // MLP layer 1 (64 -> 256), 4 output chunks x 2 row-pairs
    u64 h[4][2];
#pragma unroll
    for (int o2 = 0; o2 < 4; o2++) {
        float bb = b1[t + o2*64];
        h[o2][0] = pk(bb, bb);
        h[o2][1] = pk(bb, bb);
    }
#pragma unroll 2
    for (int c = 0; c < 64; c++) {
        u64 x0 = snp[0][c], x1p = snp[1][c];
#pragma unroll
        for (int o2 = 0; o2 < 4; o2++) {
            float w = w1[c*256 + t + o2*64];
            u64 ww = pk(w, w);
            h[o2][0] = fma2(ww, x0,  h[o2][0]);
            h[o2][1] = fma2(ww, x1p, h[o2][1]);
        }
    }
#pragma unroll
    for (int o2 = 0; o2 < 4; o2++) {
        float2 u = unpk(h[o2][0]), v = unpk(h[o2][1]);
        shp[0][t + o2*64] = pk(leaky(u.x), leaky(u.y));
        shp[1][t + o2*64] = pk(leaky(v.x), leaky(v.y));
    }
    __syncthreads();

    // MLP layer 2 (256 -> 64)
    u64 f[2] = {0ull, 0ull};
#pragma unroll 4
    for (int j = 0; j < 256; j++) {
        float w = w2[j*64 + t];
        u64 ww = pk(w, w);
        f[0] = fma2(ww, shp[0][j], f[0]);
        f[1] = fma2(ww, shp[1][j], f[1]);
    }
    const float b2t = b2[t];
    float2 f01 = unpk(f[0]), f23 = unpk(f[1]);
    float fr[4] = { f01.x, f01.y, f23.x, f23.y };
#pragma unroll
    for (int r = 0; r < 4; r++) {
        int row = row0 + r;
        int b = row / Nn, nidx = row - b * Nn;
        out[((size_t)b*Cc + t)*Nn + nidx] = x2v[r] + fr[r] + b2t;
    }
}

// ---------------- launch ----------------
extern "C" void kernel_launch(void* const* d_in, const int* in_sizes, int n_in,
                              void* d_out, int out_size)
{
    (void)in_sizes; (void)n_in; (void)out_size;
    const float* x    = (const float*)d_in[0];
    const float* y    = (const float*)d_in[1];
    const float* ln1g = (const float*)d_in[2];
    const float* ln1b = (const float*)d_in[3];
    const float* wsa1 = (const float*)d_in[4];
    const float* wsa2 = (const float*)d_in[5];
    const float* wse1 = (const float*)d_in[6];
    const float* wse2 = (const float*)d_in[7];
    const float* wout = (const float*)d_in[8];
    const float* bout = (const float*)d_in[9];
    const float* ln2g = (const float*)d_in[10];
    const float* ln2b = (const float*)d_in[11];
    const float* w1   = (const float*)d_in[12];
    const float* b1   = (const float*)d_in[13];
    const float* w2   = (const float*)d_in[14];
    const float* b2   = (const float*)d_in[15];
    float* out = (float*)d_out;

    k_ln_proj<<<Bb*Nn/4, 64>>>(x, y, ln1g, ln1b, wsa1, wsa2, wse1, wse2);
    dim3 gsec(NTILE, BH);
    k_secm_part<<<gsec, 256>>>();
    dim3 gfl(Nn/QT, BH, KSPL);
    k_flash_mma<<<gfl, 128>>>();
    dim3 gcmb(Nn/256, BH);
    k_comb<<<gcmb, 256>>>();
    k_tail<<<Bb*Nn/4, 64>>>(wout, bout, ln2g, ln2b, w1, b1, w2, b2, out);
}

// round 5
// speedup vs baseline: 2.1285x; 1.1626x over previous
#include <cuda_runtime.h>
#include <cuda_bf16.h>
#include <cstdint>

#define Bb   2
#define Cc   64
#define Nn   2304
#define Hh   4
#define Dh   16
#define BH   (Bb*Hh)
#define MLP  256
#define NTILE 18            // Nn / 128

// flash-mma tiling
#define QT    64            // queries per block (4 warps x 16 rows)
#define KT    64            // keys per smem tile
#define KSPL  4             // key splits
#define KPB   (Nn/KSPL)     // 576 keys per block
#define NTIL  (KPB/KT)      // 9 tiles
#define SKQ   24            // sK/sQ row stride (bf16) - conflict free
#define SVT   72            // sVt row stride (bf16) - conflict free

typedef unsigned long long u64;

// ---------------- scratch (device globals; no allocation) ----------------
__device__ float g_xt [Bb*Nn*Cc];
__device__ float g_y1 [BH*Nn*Dh];
__device__ float g_y2 [BH*Nn*Dh];
__device__ float g_x1 [BH*Nn*Dh];
__device__ float g_x2 [BH*Nn*Dh];
__device__ float g_secp[BH*NTILE*256];
__device__ float g_secm[BH*256];
__device__ float g_po [KSPL*BH*Nn*16];   // unnormalized attention partials
__device__ float g_pl [KSPL*BH*Nn];      // partial row sums

// ---------------- helpers ----------------
__device__ __forceinline__ float ex2a(float x) {
    float r; asm("ex2.approx.f32 %0, %1;" : "=f"(r) : "f"(x)); return r;
}
__device__ __forceinline__ uint32_t cvt_bf2(float hi, float lo) {
    uint32_t r; asm("cvt.rn.bf16x2.f32 %0, %1, %2;" : "=r"(r) : "f"(hi), "f"(lo)); return r;
}
__device__ __forceinline__ void mma16816(float d[4],
    uint32_t a0, uint32_t a1, uint32_t a2, uint32_t a3,
    uint32_t b0, uint32_t b1)
{
    asm volatile("mma.sync.aligned.m16n8k16.row.col.f32.bf16.bf16.f32 "
        "{%0,%1,%2,%3}, {%4,%5,%6,%7}, {%8,%9}, {%0,%1,%2,%3};"
        : "+f"(d[0]), "+f"(d[1]), "+f"(d[2]), "+f"(d[3])
        : "r"(a0), "r"(a1), "r"(a2), "r"(a3), "r"(b0), "r"(b1));
}
__device__ __forceinline__ u64 fma2(u64 a, u64 b, u64 c) {
    u64 d; asm("fma.rn.f32x2 %0, %1, %2, %3;" : "=l"(d) : "l"(a), "l"(b), "l"(c)); return d;
}
__device__ __forceinline__ float2 unpk(u64 v) {
    float2 r; asm("mov.b64 {%0,%1}, %2;" : "=f"(r.x), "=f"(r.y) : "l"(v)); return r;
}
__device__ __forceinline__ u64 pk(float lo, float hi) {
    u64 v; asm("mov.b64 %0, {%1,%2};" : "=l"(v) : "f"(lo), "f"(hi)); return v;
}

// ---------------- K1: transpose + LayerNorm + 4 projections ----------------
__global__ __launch_bounds__(64) void k_ln_proj(
    const float* __restrict__ x, const float* __restrict__ y,
    const float* __restrict__ g, const float* __restrict__ be,
    const float* __restrict__ wsa1, const float* __restrict__ wsa2,
    const float* __restrict__ wse1, const float* __restrict__ wse2)
{
    const int t = threadIdx.x;
    const int row0 = blockIdx.x * 4;
    __shared__ float sxn[4][64], syn[4][64];
    __shared__ float sred[2][16];

    float xv[4], yv[4];
#pragma unroll
    for (int r = 0; r < 4; r++) {
        int row = row0 + r;
        int b = row / Nn, nidx = row - b * Nn;
        xv[r] = x[((size_t)b*Cc + t)*Nn + nidx];
        yv[r] = y[((size_t)b*Cc + t)*Nn + nidx];
        g_xt[(size_t)row*Cc + t] = xv[r];
    }
    const int wid = t >> 5, lane = t & 31;
#pragma unroll
    for (int r = 0; r < 4; r++) {
        float a = xv[r], a2 = a*a, bb = yv[r], b2v = bb*bb;
#pragma unroll
        for (int o = 16; o > 0; o >>= 1) {
            a   += __shfl_xor_sync(0xffffffffu, a,   o);
            a2  += __shfl_xor_sync(0xffffffffu, a2,  o);
            bb  += __shfl_xor_sync(0xffffffffu, bb,  o);
            b2v += __shfl_xor_sync(0xffffffffu, b2v, o);
        }
        if (lane == 0) {
            sred[wid][r*4+0] = a;  sred[wid][r*4+1] = a2;
            sred[wid][r*4+2] = bb; sred[wid][r*4+3] = b2v;
        }
    }
    __syncthreads();
    const float gt = g[t], bet = be[t];
#pragma unroll
    for (int r = 0; r < 4; r++) {
        float sx  = sred[0][r*4+0] + sred[1][r*4+0];
        float sx2 = sred[0][r*4+1] + sred[1][r*4+1];
        float sy  = sred[0][r*4+2] + sred[1][r*4+2];
        float sy2 = sred[0][r*4+3] + sred[1][r*4+3];
        float mx = sx*(1.f/64.f), vx = sx2*(1.f/64.f) - mx*mx;
        float my = sy*(1.f/64.f), vy = sy2*(1.f/64.f) - my*my;
        float rx = rsqrtf(vx + 1e-5f), ry = rsqrtf(vy + 1e-5f);
        sxn[r][t] = (xv[r]-mx)*rx*gt + bet;
        syn[r][t] = (yv[r]-my)*ry*gt + bet;
    }
    __syncthreads();

    float a1[4] = {0,0,0,0}, a2a[4] = {0,0,0,0}, a3[4] = {0,0,0,0}, a4[4] = {0,0,0,0};
#pragma unroll 4
    for (int c = 0; c < 64; c++) {
        float w1v = wsa1[c*64+t], w2v = wsa2[c*64+t];
        float w3v = wse1[c*64+t], w4v = wse2[c*64+t];
#pragma unroll
        for (int r = 0; r < 4; r++) {
            float yc = syn[r][c], xc = sxn[r][c];
            a1[r]  = fmaf(yc, w1v, a1[r]);
            a2a[r] = fmaf(yc, w2v, a2a[r]);
            a3[r]  = fmaf(xc, w3v, a3[r]);
            a4[r]  = fmaf(xc, w4v, a4[r]);
        }
    }
    const int h = t >> 4, d = t & 15;
#pragma unroll
    for (int r = 0; r < 4; r++) {
        int row = row0 + r;
        int b = row / Nn, nidx = row - b * Nn;
        size_t o = ((size_t)(b*Hh + h)*Nn + nidx)*Dh + d;
        g_y1[o] = a1[r]; g_y2[o] = a2a[r];
        g_x1[o] = a3[r]; g_x2[o] = a4[r];
    }
}

// ---------------- K2a: channel-attn logits, partial over n-tiles ----------------
__global__ __launch_bounds__(256) void k_secm_part()
{
    const int bh = blockIdx.y, nb = blockIdx.x;
    const int t = threadIdx.x, i = t >> 4, j = t & 15;
    const float* __restrict__ x1 = g_x1 + (size_t)bh*Nn*Dh;
    const float* __restrict__ x2 = g_x2 + (size_t)bh*Nn*Dh;
    const int n0 = nb * 128;
    float s = 0.f;
#pragma unroll 4
    for (int n = n0; n < n0 + 128; n++)
        s = fmaf(x1[n*16 + i], x2[n*16 + j], s);
    g_secp[((size_t)bh*NTILE + nb)*256 + t] = s;
}

// ---------------- K2b: reduce partials + softmax (16x16 per bh) ----------------
__global__ __launch_bounds__(256) void k_secm_soft()
{
    const int bh = blockIdx.x;
    const int t = threadIdx.x, i = t >> 4;
    float s = 0.f;
#pragma unroll
    for (int k = 0; k < NTILE; k++)
        s += g_secp[((size_t)bh*NTILE + k)*256 + t];
    s *= (0.25f / 144.0f);
    __shared__ float sm[16][16], se[16][16];
    sm[i][t & 15] = s;
    __syncthreads();
    float rmax = -1e30f;
#pragma unroll
    for (int k = 0; k < 16; k++) rmax = fmaxf(rmax, sm[i][k]);
    float e = __expf(s - rmax);
    se[i][t & 15] = e;
    __syncthreads();
    float rs = 0.f;
#pragma unroll
    for (int k = 0; k < 16; k++) rs += se[i][k];
    g_secm[bh*256 + t] = e / rs;
}

// ---------------- K3: flash attention via bf16 mma.sync, double-buffered ----------------
// grid (Nn/QT=36, BH, KSPL), 128 threads = 4 warps, 16 query rows per warp.
__global__ __launch_bounds__(128) void k_flash_mma()
{
    const int qt = blockIdx.x, bh = blockIdx.y, ks = blockIdx.z;
    const int t = threadIdx.x, wid = t >> 5, lane = t & 31;
    const int g = lane >> 2, tg = lane & 3;

    __shared__ __align__(16) __nv_bfloat16 sQ [QT*SKQ];
    __shared__ __align__(16) __nv_bfloat16 sK [2][KT*SKQ];
    __shared__ __align__(16) __nv_bfloat16 sVt[2][16*SVT];

    const float* __restrict__ Qb = g_y1 + (size_t)bh*Nn*Dh;
    const float* __restrict__ Kb = g_y2 + (size_t)bh*Nn*Dh;
    const float* __restrict__ Vb = g_x1 + (size_t)bh*Nn*Dh;

    // Q tile -> bf16 smem (rows stride SKQ)
    {
        const float4* src = (const float4*)(Qb + (size_t)qt*QT*16);
#pragma unroll
        for (int i = t; i < QT*4; i += 128) {
            float4 v = src[i];
            int key = i >> 2, dq = (i & 3) * 4;
            __nv_bfloat16* d = sQ + key*SKQ + dq;
            d[0] = __float2bfloat16(v.x); d[1] = __float2bfloat16(v.y);
            d[2] = __float2bfloat16(v.z); d[3] = __float2bfloat16(v.w);
        }
    }

    // preload tile 0 into buffer 0
    {
        const int key0 = ks*KPB;
        const float4* srcK = (const float4*)(Kb + (size_t)key0*16);
        const float4* srcV = (const float4*)(Vb + (size_t)key0*16);
#pragma unroll
        for (int i = t; i < KT*4; i += 128) {
            float4 kv = srcK[i];
            int key = i >> 2, dq = (i & 3) * 4;
            __nv_bfloat16* d = sK[0] + key*SKQ + dq;
            d[0] = __float2bfloat16(kv.x); d[1] = __float2bfloat16(kv.y);
            d[2] = __float2bfloat16(kv.z); d[3] = __float2bfloat16(kv.w);
            float4 vv = srcV[i];
            sVt[0][(dq+0)*SVT + key] = __float2bfloat16(vv.x);
            sVt[0][(dq+1)*SVT + key] = __float2bfloat16(vv.y);
            sVt[0][(dq+2)*SVT + key] = __float2bfloat16(vv.z);
            sVt[0][(dq+3)*SVT + key] = __float2bfloat16(vv.w);
        }
    }
    __syncthreads();

    // per-warp Q A-fragment (rows wid*16 .. +15), reused all tiles
    const int qr = wid * 16;
    uint32_t qa0 = *(const uint32_t*)(sQ + (qr+g  )*SKQ + 2*tg);
    uint32_t qa1 = *(const uint32_t*)(sQ + (qr+g+8)*SKQ + 2*tg);
    uint32_t qa2 = *(const uint32_t*)(sQ + (qr+g  )*SKQ + 2*tg + 8);
    uint32_t qa3 = *(const uint32_t*)(sQ + (qr+g+8)*SKQ + 2*tg + 8);

    float o[2][4] = {{0,0,0,0},{0,0,0,0}};
    float lsum_lo = 0.f, lsum_hi = 0.f;
    const float SC = 0.25f * 1.4426950408889634f;   // scale * log2(e)

    for (int kt = 0; kt < NTIL; kt++) {
        const int cur = kt & 1;
        const bool more = (kt + 1 < NTIL);

        // prefetch next tile to registers
        float4 kreg[2], vreg[2];
        if (more) {
            const int key0 = ks*KPB + (kt+1)*KT;
            const float4* srcK = (const float4*)(Kb + (size_t)key0*16);
            const float4* srcV = (const float4*)(Vb + (size_t)key0*16);
#pragma unroll
            for (int u = 0; u < 2; u++) {
                kreg[u] = srcK[t + u*128];
                vreg[u] = srcV[t + u*128];
            }
        }

        const __nv_bfloat16* kb_s = sK[cur];
        const __nv_bfloat16* vb_s = sVt[cur];

        // S = Q K^T  (16 x 64), 8 n-tiles of 8 keys
        float s[8][4];
        uint32_t p[8][2];
#pragma unroll
        for (int n = 0; n < 8; n++) {
            s[n][0] = s[n][1] = s[n][2] = s[n][3] = 0.f;
            uint32_t b0 = *(const uint32_t*)(kb_s + (n*8+g)*SKQ + 2*tg);
            uint32_t b1 = *(const uint32_t*)(kb_s + (n*8+g)*SKQ + 2*tg + 8);
            mma16816(s[n], qa0, qa1, qa2, qa3, b0, b1);
        }
        // exp (max-free: logits tiny by construction) + pack to bf16 P frags
#pragma unroll
        for (int n = 0; n < 8; n++) {
            float e0 = ex2a(s[n][0]*SC), e1 = ex2a(s[n][1]*SC);
            float e2 = ex2a(s[n][2]*SC), e3 = ex2a(s[n][3]*SC);
            lsum_lo += e0 + e1;  lsum_hi += e2 + e3;
            p[n][0] = cvt_bf2(e1, e0);   // low = col 2tg
            p[n][1] = cvt_bf2(e3, e2);
        }
        // O += P V  (4 k-tiles of 16 keys, 2 n-tiles of 8 dims)
#pragma unroll
        for (int kk = 0; kk < 4; kk++) {
            uint32_t a0 = p[2*kk][0],   a1 = p[2*kk][1];
            uint32_t a2 = p[2*kk+1][0], a3 = p[2*kk+1][1];
#pragma unroll
            for (int n = 0; n < 2; n++) {
                uint32_t b0 = *(const uint32_t*)(vb_s + (n*8+g)*SVT + kk*16 + 2*tg);
                uint32_t b1 = *(const uint32_t*)(vb_s + (n*8+g)*SVT + kk*16 + 2*tg + 8);
                mma16816(o[n], a0, a1, a2, a3, b0, b1);
            }
        }

        // store prefetched tile into the other buffer
        if (more) {
            const int nxt = cur ^ 1;
#pragma unroll
            for (int u = 0; u < 2; u++) {
                int i = t + u*128;
                int key = i >> 2, dq = (i & 3) * 4;
                __nv_bfloat16* d = sK[nxt] + key*SKQ + dq;
                d[0] = __float2bfloat16(kreg[u].x); d[1] = __float2bfloat16(kreg[u].y);
                d[2] = __float2bfloat16(kreg[u].z); d[3] = __float2bfloat16(kreg[u].w);
                sVt[nxt][(dq+0)*SVT + key] = __float2bfloat16(vreg[u].x);
                sVt[nxt][(dq+1)*SVT + key] = __float2bfloat16(vreg[u].y);
                sVt[nxt][(dq+2)*SVT + key] = __float2bfloat16(vreg[u].z);
                sVt[nxt][(dq+3)*SVT + key] = __float2bfloat16(vreg[u].w);
            }
            __syncthreads();
        }
    }

    // reduce row sums across the 4 lanes of each group
    lsum_lo += __shfl_xor_sync(0xffffffffu, lsum_lo, 1);
    lsum_lo += __shfl_xor_sync(0xffffffffu, lsum_lo, 2);
    lsum_hi += __shfl_xor_sync(0xffffffffu, lsum_hi, 1);
    lsum_hi += __shfl_xor_sync(0xffffffffu, lsum_hi, 2);

    // write partials
    const int q_lo = qt*QT + qr + g;
    const int q_hi = q_lo + 8;
    float* po = g_po + ((size_t)(ks*BH + bh)*Nn)*16;
#pragma unroll
    for (int n = 0; n < 2; n++) {
        po[(size_t)q_lo*16 + n*8 + 2*tg    ] = o[n][0];
        po[(size_t)q_lo*16 + n*8 + 2*tg + 1] = o[n][1];
        po[(size_t)q_hi*16 + n*8 + 2*tg    ] = o[n][2];
        po[(size_t)q_hi*16 + n*8 + 2*tg + 1] = o[n][3];
    }
    if (tg == 0) {
        g_pl[(size_t)(ks*BH + bh)*Nn + q_lo] = lsum_lo;
        g_pl[(size_t)(ks*BH + bh)*Nn + q_hi] = lsum_hi;
    }
}

// ---------------- K4: combine splits + epilogue + out-proj + LN2 + MLP ----------------
__device__ __forceinline__ float leaky(float h) { return h > 0.f ? h : 0.01f * h; }

__global__ __launch_bounds__(64) void k_tail(
    const float* __restrict__ wout, const float* __restrict__ bout,
    const float* __restrict__ g2,   const float* __restrict__ be2,
    const float* __restrict__ w1,   const float* __restrict__ b1,
    const float* __restrict__ w2,   const float* __restrict__ b2,
    float* __restrict__ out)
{
    const int t = threadIdx.x;
    const int row0 = blockIdx.x * 4;
    const int b = row0 / Nn;
    const int n0 = row0 - b*Nn;
    const int h = t >> 4, d = t & 15;
    const int bh = b*Hh + h;

    __shared__ float ssec[4][256];
    __shared__ float sq[4][64];
    __shared__ float sinvl[4][4];
    __shared__ u64 sop[2][64];   // attn-out rows packed (0,1),(2,3)
    __shared__ u64 snp[2][64];   // normalized rows packed
    __shared__ u64 shp[2][256];  // hidden rows packed
    __shared__ float sred[2][8];

    // channel softmax maps for the 4 heads of this batch
#pragma unroll
    for (int k = 0; k < 16; k++) {
        int idx = k*64 + t;
        ssec[idx >> 8][idx & 255] = g_secm[(b*Hh + (idx >> 8))*256 + (idx & 255)];
    }
    // Q rows (y1) for the 4 rows
#pragma unroll
    for (int r = 0; r < 4; r++)
        sq[r][t] = g_y1[((size_t)bh*Nn + n0 + r)*16 + d];
    // inverse row sums
    if (t < 16) {
        int r = t >> 2, hh = t & 3;
        float l = 0.f;
#pragma unroll
        for (int ks = 0; ks < KSPL; ks++)
            l += g_pl[(size_t)(ks*BH + b*Hh + hh)*Nn + n0 + r];
        sinvl[r][hh] = 1.0f / l;
    }
    __syncthreads();

    // combine po splits + channel-map epilogue -> attn output channel t per row
    float soval[4];
#pragma unroll
    for (int r = 0; r < 4; r++) {
        float pv = 0.f;
#pragma unroll
        for (int ks = 0; ks < KSPL; ks++)
            pv += g_po[((size_t)(ks*BH + bh)*Nn + n0 + r)*16 + d];
        float o2 = 0.f;
#pragma unroll
        for (int i = 0; i < 16; i++)
            o2 = fmaf(sq[r][h*16 + i], ssec[h][i*16 + d], o2);
        soval[r] = pv * sinvl[r][h] * o2;
    }
    sop[0][t] = pk(soval[0], soval[1]);
    sop[1][t] = pk(soval[2], soval[3]);
    __syncthreads();

    u64 ac[2] = {0ull, 0ull};
#pragma unroll 4
    for (int c = 0; c < 64; c++) {
        float w = wout[c*64 + t];
        u64 ww = pk(w, w);
        ac[0] = fma2(ww, sop[0][c], ac[0]);
        ac[1] = fma2(ww, sop[1][c], ac[1]);
    }
    const float bo = bout[t];
    float2 a01 = unpk(ac[0]), a23 = unpk(ac[1]);
    float x2v[4];
    x2v[0] = g_xt[(size_t)(row0+0)*64 + t] + a01.x + bo;
    x2v[1] = g_xt[(size_t)(row0+1)*64 + t] + a01.y + bo;
    x2v[2] = g_xt[(size_t)(row0+2)*64 + t] + a23.x + bo;
    x2v[3] = g_xt[(size_t)(row0+3)*64 + t] + a23.y + bo;

    const int wid = t >> 5, lane = t & 31;
#pragma unroll
    for (int r = 0; r < 4; r++) {
        float a = x2v[r], a2 = a*a;
#pragma unroll
        for (int o = 16; o > 0; o >>= 1) {
            a  += __shfl_xor_sync(0xffffffffu, a,  o);
            a2 += __shfl_xor_sync(0xffffffffu, a2, o);
        }
        if (lane == 0) { sred[wid][r*2] = a; sred[wid][r*2+1] = a2; }
    }
    __syncthreads();
    const float g2t = g2[t], be2t = be2[t];
    float snv[4];
#pragma unroll
    for (int r = 0; r < 4; r++) {
        float sxx = sred[0][r*2] + sred[1][r*2];
        float sq2 = sred[0][r*2+1] + sred[1][r*2+1];
        float m = sxx*(1.f/64.f), v = sq2*(1.f/64.f) - m*m;
        snv[r] = (x2v[r]-m)*rsqrtf(v + 1e-5f)*g2t + be2t;
    }
    snp[0][t] = pk(snv[0], snv[1]);
    snp[1][t] = pk(snv[2], snv[3]);
    __syncthreads();

    // MLP layer 1 (64 -> 256), 4 output chunks x 2 row-pairs
    u64 hh[4][2];
#pragma unroll
    for (int o2 = 0; o2 < 4; o2++) {
        float bb = b1[t + o2*64];
        hh[o2][0] = pk(bb, bb);
        hh[o2][1] = pk(bb, bb);
    }
#pragma unroll 2
    for (int c = 0; c < 64; c++) {
        u64 x0 = snp[0][c], x1p = snp[1][c];
#pragma unroll
        for (int o2 = 0; o2 < 4; o2++) {
            float w = w1[c*256 + t + o2*64];
            u64 ww = pk(w, w);
            hh[o2][0] = fma2(ww, x0,  hh[o2][0]);
            hh[o2][1] = fma2(ww, x1p, hh[o2][1]);
        }
    }
#pragma unroll
    for (int o2 = 0; o2 < 4; o2++) {
        float2 u = unpk(hh[o2][0]), v = unpk(hh[o2][1]);
        shp[0][t + o2*64] = pk(leaky(u.x), leaky(u.y));
        shp[1][t + o2*64] = pk(leaky(v.x), leaky(v.y));
    }
    __syncthreads();

    // MLP layer 2 (256 -> 64)
    u64 f[2] = {0ull, 0ull};
#pragma unroll 4
    for (int j = 0; j < 256; j++) {
        float w = w2[j*64 + t];
        u64 ww = pk(w, w);
        f[0] = fma2(ww, shp[0][j], f[0]);
        f[1] = fma2(ww, shp[1][j], f[1]);
    }
    const float b2t = b2[t];
    float2 f01 = unpk(f[0]), f23 = unpk(f[1]);
    float fr[4] = { f01.x, f01.y, f23.x, f23.y };
#pragma unroll
    for (int r = 0; r < 4; r++)
        out[((size_t)b*Cc + t)*Nn + n0 + r] = x2v[r] + fr[r] + b2t;
}

// ---------------- launch ----------------
extern "C" void kernel_launch(void* const* d_in, const int* in_sizes, int n_in,
                              void* d_out, int out_size)
{
    (void)in_sizes; (void)n_in; (void)out_size;
    const float* x    = (const float*)d_in[0];
    const float* y    = (const float*)d_in[1];
    const float* ln1g = (const float*)d_in[2];
    const float* ln1b = (const float*)d_in[3];
    const float* wsa1 = (const float*)d_in[4];
    const float* wsa2 = (const float*)d_in[5];
    const float* wse1 = (const float*)d_in[6];
    const float* wse2 = (const float*)d_in[7];
    const float* wout = (const float*)d_in[8];
    const float* bout = (const float*)d_in[9];
    const float* ln2g = (const float*)d_in[10];
    const float* ln2b = (const float*)d_in[11];
    const float* w1   = (const float*)d_in[12];
    const float* b1   = (const float*)d_in[13];
    const float* w2   = (const float*)d_in[14];
    const float* b2   = (const float*)d_in[15];
    float* out = (float*)d_out;

    k_ln_proj<<<Bb*Nn/4, 64>>>(x, y, ln1g, ln1b, wsa1, wsa2, wse1, wse2);
    dim3 gsec(NTILE, BH);
    k_secm_part<<<gsec, 256>>>();
    k_secm_soft<<<BH, 256>>>();
    dim3 gfl(Nn/QT, BH, KSPL);
    k_flash_mma<<<gfl, 128>>>();
    k_tail<<<Bb*Nn/4, 64>>>(wout, bout, ln2g, ln2b, w1, b1, w2, b2, out);
}